// round 7
// baseline (speedup 1.0000x reference)
#include <cuda_runtime.h>
#include <cstdint>

#define B_    64
#define T_    512
#define H_    8
#define D_    32
#define C_    256
#define M_    (B_*T_)
#define NTOT  24576
#define QKV_ELEMS (M_*C_)

__device__ float g_qkv[3 * QKV_ELEMS];   // q,k,v each [token][256] row-major
__device__ float g_y[M_ * C_];           // attention out [b*T+t][h*32+d]

// ---------------- mma.sync tf32 helpers --------------------------------------
__device__ __forceinline__ uint32_t f2tf32(float f) {
    uint32_t u; asm("cvt.rna.tf32.f32 %0, %1;" : "=r"(u) : "f"(f)); return u;
}
__device__ __forceinline__ void mma8(float* d, const uint32_t* a, uint32_t b0, uint32_t b1) {
    asm volatile(
        "mma.sync.aligned.m16n8k8.row.col.f32.tf32.tf32.f32 "
        "{%0,%1,%2,%3},{%4,%5,%6,%7},{%8,%9},{%0,%1,%2,%3};"
        : "+f"(d[0]), "+f"(d[1]), "+f"(d[2]), "+f"(d[3])
        : "r"(a[0]), "r"(a[1]), "r"(a[2]), "r"(a[3]), "r"(b0), "r"(b1));
}

// ---------------------------------------------------------------------------
// tf32 GEMM: C[128,128] = gather(A)[128,256] @ W[n0:,256]^T + bias
// BK=32 double-buffered. k-permuted layout: within each 8-word k-group,
// word kw sits at (kw&3)*2 + (kw>>2); lanes fetch pair {c, c+4} with one
// LDS.64. Row stride 40 -> conflict-free 64-bit fragment loads.
// ---------------------------------------------------------------------------
#define GSM_STRIDE 40
#define GSM_BUF (128 * GSM_STRIDE)
#define GEMM_SMEM (4 * GSM_BUF * 4)     // 81920 bytes

__device__ __forceinline__ void gemm_tc_core(
    const float* __restrict__ A, const int* __restrict__ gidx,
    const float* __restrict__ W, const float* __restrict__ bias,
    float* __restrict__ outp, int m0, int n0, uint32_t* smg)
{
    uint32_t* As = smg;                  // [2][128*40]
    uint32_t* Ws = smg + 2 * GSM_BUF;

    const int tid = threadIdx.x;
    const int rb = tid >> 3;             // 0..31
    const int kq = tid & 7;              // float4 within 32-k chunk

    const float* arp[4];
    const float* wrp[4];
    int sofs[4];
#pragma unroll
    for (int l = 0; l < 4; l++) {
        int r = rb + 32 * l;
        arp[l] = A + (size_t)gidx[m0 + r] * 256 + kq * 4;
        wrp[l] = W + (size_t)(n0 + r) * 256 + kq * 4;
        sofs[l] = r * GSM_STRIDE + (kq >> 1) * 8 + (kq & 1);   // permuted base
    }

    float4 va[4], vw[4];
    auto load_regs = [&](int c) {
        const int k0 = c * 32;
#pragma unroll
        for (int l = 0; l < 4; l++) {
            va[l] = *(const float4*)(arp[l] + k0);
            vw[l] = *(const float4*)(wrp[l] + k0);
        }
    };
    auto store_smem = [&](int buf) {
        uint32_t* Ab = As + buf * GSM_BUF;
        uint32_t* Wb = Ws + buf * GSM_BUF;
#pragma unroll
        for (int l = 0; l < 4; l++) {
            uint32_t* pa = Ab + sofs[l];
            pa[0] = f2tf32(va[l].x); pa[2] = f2tf32(va[l].y);
            pa[4] = f2tf32(va[l].z); pa[6] = f2tf32(va[l].w);
            uint32_t* pw = Wb + sofs[l];
            pw[0] = f2tf32(vw[l].x); pw[2] = f2tf32(vw[l].y);
            pw[4] = f2tf32(vw[l].z); pw[6] = f2tf32(vw[l].w);
        }
    };

    const int warp = tid >> 5, lane = tid & 31;
    const int g = lane >> 2, c = lane & 3;
    const int wm = warp >> 2, wn = warp & 3;
    const int mb = wm * 64, nb = wn * 32;

    float acc[4][4][4];
#pragma unroll
    for (int mi = 0; mi < 4; mi++)
#pragma unroll
        for (int ni = 0; ni < 4; ni++)
#pragma unroll
            for (int t = 0; t < 4; t++) acc[mi][ni][t] = 0.f;

    load_regs(0);
    store_smem(0);
    __syncthreads();

    for (int ch = 0; ch < 8; ch++) {
        if (ch < 7) load_regs(ch + 1);

        const uint32_t* Ab = As + (ch & 1) * GSM_BUF;
        const uint32_t* Wb = Ws + (ch & 1) * GSM_BUF;
#pragma unroll
        for (int kt = 0; kt < 4; kt++) {
            const int kc = kt * 8 + c * 2;
            uint32_t af[4][4];
#pragma unroll
            for (int mi = 0; mi < 4; mi++) {
                const int r = mb + mi * 16 + g;
                uint2 a0 = *(const uint2*)&Ab[r * GSM_STRIDE + kc];
                uint2 a1 = *(const uint2*)&Ab[(r + 8) * GSM_STRIDE + kc];
                af[mi][0] = a0.x; af[mi][1] = a1.x;
                af[mi][2] = a0.y; af[mi][3] = a1.y;
            }
            uint2 bf[4];
#pragma unroll
            for (int ni = 0; ni < 4; ni++)
                bf[ni] = *(const uint2*)&Wb[(nb + ni * 8 + g) * GSM_STRIDE + kc];
#pragma unroll
            for (int mi = 0; mi < 4; mi++)
#pragma unroll
                for (int ni = 0; ni < 4; ni++)
                    mma8(acc[mi][ni], af[mi], bf[ni].x, bf[ni].y);
        }

        if (ch < 7) {
            store_smem((ch + 1) & 1);
            __syncthreads();
        }
    }

    float2 bz[4];
#pragma unroll
    for (int ni = 0; ni < 4; ni++)
        bz[ni] = *(const float2*)&bias[n0 + nb + ni * 8 + 2 * c];

#pragma unroll
    for (int mi = 0; mi < 4; mi++) {
        const int mA = m0 + mb + mi * 16 + g;
        const int mB = mA + 8;
#pragma unroll
        for (int ni = 0; ni < 4; ni++) {
            const int n = n0 + nb + ni * 8 + 2 * c;
            float2 v0 = make_float2(acc[mi][ni][0] + bz[ni].x, acc[mi][ni][1] + bz[ni].y);
            float2 v1 = make_float2(acc[mi][ni][2] + bz[ni].x, acc[mi][ni][3] + bz[ni].y);
            *(float2*)&outp[(size_t)mA * 256 + n] = v0;
            *(float2*)&outp[(size_t)mB * 256 + n] = v1;
        }
    }
}

__global__ __launch_bounds__(256, 2) void gemm_qkv_tc(
    const float* __restrict__ x, const int* __restrict__ pidx,
    const float* __restrict__ Wq, const float* __restrict__ Wk, const float* __restrict__ Wv,
    const float* __restrict__ bq, const float* __restrict__ bk, const float* __restrict__ bv)
{
    extern __shared__ uint32_t smg[];
    const int z = blockIdx.z;
    const float* W  = (z == 0) ? Wq : (z == 1 ? Wk : Wv);
    const float* bi = (z == 0) ? bq : (z == 1 ? bk : bv);
    gemm_tc_core(x, pidx, W, bi, g_qkv + (size_t)z * QKV_ELEMS,
                 blockIdx.x * 128, blockIdx.y * 128, smg);
}

__global__ __launch_bounds__(256, 2) void gemm_proj_tc(
    const int* __restrict__ pinv, const float* __restrict__ Wp,
    const float* __restrict__ bp, float* __restrict__ out)
{
    extern __shared__ uint32_t smg[];
    gemm_tc_core(g_y, pinv, Wp, bp, out, blockIdx.x * 128, blockIdx.y * 128, smg);
}

// ---------------------------------------------------------------------------
// Attention: 512 threads (16 warps x 32 queries).
// Ks [512][40] k-permuted (LDS.64 B-frags, conflict-free),
// Vs [512][36] identity (scalar reads, 2-way), Ps per-warp [16][68]
// (indices <= 63 < 68 -- overflow bug from round 6 fixed).
// ---------------------------------------------------------------------------
#define KS_OFF 0
#define VS_OFF (512*40)
#define PS_OFF (VS_OFF + 512*36)
#define SEG_OFF (PS_OFF + 16*1088)
#define ATTN_SMEM ((SEG_OFF + 512) * 4)    // 227328 bytes

__global__ __launch_bounds__(512, 1) void attn_kernel(const int* __restrict__ pbatch)
{
    extern __shared__ uint32_t sm[];
    uint32_t* Ks = sm + KS_OFF;
    uint32_t* Vs = sm + VS_OFF;
    uint32_t* Ps = sm + PS_OFF;
    int*      seg = (int*)(sm + SEG_OFF);

    const int h = blockIdx.x, b = blockIdx.y;
    const float* __restrict__ Qb = g_qkv + (size_t)(b * 512) * 256 + h * 32;
    const float* __restrict__ Kb = Qb + QKV_ELEMS;
    const float* __restrict__ Vb = Qb + 2 * (size_t)QKV_ELEMS;

    const int tid = threadIdx.x;

#pragma unroll
    for (int it = 0; it < 8; it++) {
        int idx = tid + it * 512;          // 0..4095
        int j = idx >> 3, d4g = idx & 7;
        float4 kv = *(const float4*)(Kb + (size_t)j * 256 + d4g * 4);
        float4 vv = *(const float4*)(Vb + (size_t)j * 256 + d4g * 4);
        uint32_t* kp = Ks + j * 40 + (d4g >> 1) * 8 + (d4g & 1);
        kp[0] = f2tf32(kv.x); kp[2] = f2tf32(kv.y);
        kp[4] = f2tf32(kv.z); kp[6] = f2tf32(kv.w);
        uint32_t* vp = Vs + j * 36 + d4g * 4;
        vp[0] = f2tf32(vv.x); vp[1] = f2tf32(vv.y);
        vp[2] = f2tf32(vv.z); vp[3] = f2tf32(vv.w);
    }
    if (tid < 512) seg[tid] = pbatch[b * 512 + tid];
    __syncthreads();

    const int warp = tid >> 5, lane = tid & 31;
    const int g = lane >> 2, c = lane & 3;
    uint32_t* Pw = Ps + warp * 1088;       // [16][68]
    const float scale = 0.17677669529663688f;
    const int jw0 = 2 * c, jw1 = 2 * c + 1;
    const int pos0 = (jw0 & 3) * 2 + (jw0 >> 2);
    const int pos1 = (jw1 & 3) * 2 + (jw1 >> 2);

    for (int grp = 0; grp < 2; grp++) {
        const int q0 = warp * 32 + grp * 16;
        const int r0 = q0 + g, r1 = q0 + g + 8;
        const float* Q0 = Qb + (size_t)r0 * 256;
        const float* Q1 = Qb + (size_t)r1 * 256;

        uint32_t aq[4][4];
#pragma unroll
        for (int kt = 0; kt < 4; kt++) {
            aq[kt][0] = f2tf32(Q0[kt*8 + c] * scale);
            aq[kt][1] = f2tf32(Q1[kt*8 + c] * scale);
            aq[kt][2] = f2tf32(Q0[kt*8 + c + 4] * scale);
            aq[kt][3] = f2tf32(Q1[kt*8 + c + 4] * scale);
        }
        const int sq0 = seg[r0], sq1 = seg[r1];

        float m0 = -1e30f, m1 = -1e30f, l0 = 0.f, l1 = 0.f;
        float y[4][4];
#pragma unroll
        for (int n = 0; n < 4; n++)
#pragma unroll
            for (int r = 0; r < 4; r++) y[n][r] = 0.f;

        for (int ch = 0; ch < 8; ch++) {
            const int j0 = ch * 64;
            float s[8][4];
#pragma unroll
            for (int nt = 0; nt < 8; nt++) {
                s[nt][0] = s[nt][1] = s[nt][2] = s[nt][3] = 0.f;
                const int jb = (j0 + nt*8 + g) * 40;
#pragma unroll
                for (int kt = 0; kt < 4; kt++) {
                    uint2 kk = *(const uint2*)&Ks[jb + kt*8 + c*2];
                    mma8(s[nt], aq[kt], kk.x, kk.y);
                }
            }

            float cm0 = m0, cm1 = m1;
#pragma unroll
            for (int nt = 0; nt < 8; nt++) {
                const int jA = j0 + nt*8 + 2*c;
                const int sA = seg[jA], sB = seg[jA + 1];
                if (sA == sq0) s[nt][0] = -1e9f;
                if (sB == sq0) s[nt][1] = -1e9f;
                if (sA == sq1) s[nt][2] = -1e9f;
                if (sB == sq1) s[nt][3] = -1e9f;
                cm0 = fmaxf(cm0, fmaxf(s[nt][0], s[nt][1]));
                cm1 = fmaxf(cm1, fmaxf(s[nt][2], s[nt][3]));
            }
            cm0 = fmaxf(cm0, __shfl_xor_sync(0xffffffffu, cm0, 1));
            cm0 = fmaxf(cm0, __shfl_xor_sync(0xffffffffu, cm0, 2));
            cm1 = fmaxf(cm1, __shfl_xor_sync(0xffffffffu, cm1, 1));
            cm1 = fmaxf(cm1, __shfl_xor_sync(0xffffffffu, cm1, 2));

            const float a0 = __expf(m0 - cm0), a1 = __expf(m1 - cm1);
            m0 = cm0; m1 = cm1;
            l0 *= a0; l1 *= a1;
#pragma unroll
            for (int n = 0; n < 4; n++) {
                y[n][0] *= a0; y[n][1] *= a0;
                y[n][2] *= a1; y[n][3] *= a1;
            }

            float ps0 = 0.f, ps1 = 0.f;
#pragma unroll
            for (int nt = 0; nt < 8; nt++) {
                float p0 = __expf(s[nt][0] - m0);
                float p1 = __expf(s[nt][1] - m0);
                float p2 = __expf(s[nt][2] - m1);
                float p3 = __expf(s[nt][3] - m1);
                ps0 += p0 + p1; ps1 += p2 + p3;
                Pw[g*68      + nt*8 + pos0] = f2tf32(p0);
                Pw[g*68      + nt*8 + pos1] = f2tf32(p1);
                Pw[(g+8)*68  + nt*8 + pos0] = f2tf32(p2);
                Pw[(g+8)*68  + nt*8 + pos1] = f2tf32(p3);
            }
            l0 += ps0; l1 += ps1;
            __syncwarp();

#pragma unroll
            for (int kt2 = 0; kt2 < 8; kt2++) {
                uint2 u0 = *(const uint2*)&Pw[g*68     + kt2*8 + c*2];
                uint2 u1 = *(const uint2*)&Pw[(g+8)*68 + kt2*8 + c*2];
                uint32_t ap[4] = {u0.x, u1.x, u0.y, u1.y};
                const int vb0 = (j0 + kt2*8 + c) * 36 + g;
                const int vb1 = (j0 + kt2*8 + c + 4) * 36 + g;
#pragma unroll
                for (int nt2 = 0; nt2 < 4; nt2++)
                    mma8(y[nt2], ap, Vs[vb0 + nt2*8], Vs[vb1 + nt2*8]);
            }
            __syncwarp();
        }

        l0 += __shfl_xor_sync(0xffffffffu, l0, 1);
        l0 += __shfl_xor_sync(0xffffffffu, l0, 2);
        l1 += __shfl_xor_sync(0xffffffffu, l1, 1);
        l1 += __shfl_xor_sync(0xffffffffu, l1, 2);
        const float inv0 = 1.0f / l0, inv1 = 1.0f / l1;

        float* O0 = g_y + (size_t)(b * 512 + r0) * 256 + h * 32;
        float* O1 = g_y + (size_t)(b * 512 + r1) * 256 + h * 32;
#pragma unroll
        for (int nt2 = 0; nt2 < 4; nt2++) {
            float2 v0 = make_float2(y[nt2][0] * inv0, y[nt2][1] * inv0);
            float2 v1 = make_float2(y[nt2][2] * inv1, y[nt2][3] * inv1);
            *(float2*)&O0[nt2*8 + 2*c] = v0;
            *(float2*)&O1[nt2*8 + 2*c] = v1;
        }
    }
}

// ---------------------------------------------------------------------------

extern "C" void kernel_launch(void* const* d_in, const int* in_sizes, int n_in,
                              void* d_out, int out_size)
{
    const float* x    = (const float*)d_in[0];
    const float* Wq   = (const float*)d_in[1];
    const float* bq   = (const float*)d_in[2];
    const float* Wk   = (const float*)d_in[3];
    const float* bk   = (const float*)d_in[4];
    const float* Wv   = (const float*)d_in[5];
    const float* bv   = (const float*)d_in[6];
    const float* Wp   = (const float*)d_in[7];
    const float* bp   = (const float*)d_in[8];
    const int* pidx   = (const int*)d_in[9];
    const int* pbatch = (const int*)d_in[10];
    const int* pinv   = (const int*)d_in[11];
    float* out = (float*)d_out;

    cudaFuncSetAttribute(gemm_qkv_tc,  cudaFuncAttributeMaxDynamicSharedMemorySize, GEMM_SMEM);
    cudaFuncSetAttribute(gemm_proj_tc, cudaFuncAttributeMaxDynamicSharedMemorySize, GEMM_SMEM);
    cudaFuncSetAttribute(attn_kernel,  cudaFuncAttributeMaxDynamicSharedMemorySize, ATTN_SMEM);

    gemm_qkv_tc<<<dim3(M_ / 128, 2, 3), 256, GEMM_SMEM>>>(x, pidx, Wq, Wk, Wv, bq, bk, bv);
    attn_kernel<<<dim3(H_, B_), 512, ATTN_SMEM>>>(pbatch);
    gemm_proj_tc<<<dim3(NTOT / 128, 2), 256, GEMM_SMEM>>>(pinv, Wp, bp, out);
}

// round 8
// speedup vs baseline: 1.1958x; 1.1958x over previous
#include <cuda_runtime.h>
#include <cstdint>

#define B_    64
#define T_    512
#define H_    8
#define D_    32
#define C_    256
#define M_    (B_*T_)
#define NTOT  24576
#define QKV_ELEMS (M_*C_)

__device__ float g_qkv[3 * QKV_ELEMS];   // q,k,v each [token][256] row-major
__device__ float g_y[M_ * C_];           // attention out [b*T+t][h*32+d]

// ---------------- mma.sync tf32 helpers --------------------------------------
__device__ __forceinline__ uint32_t f2tf32(float f) {
    uint32_t u; asm("cvt.rna.tf32.f32 %0, %1;" : "=r"(u) : "f"(f)); return u;
}
__device__ __forceinline__ void mma8(float* d, const uint32_t* a, uint32_t b0, uint32_t b1) {
    asm volatile(
        "mma.sync.aligned.m16n8k8.row.col.f32.tf32.tf32.f32 "
        "{%0,%1,%2,%3},{%4,%5,%6,%7},{%8,%9},{%0,%1,%2,%3};"
        : "+f"(d[0]), "+f"(d[1]), "+f"(d[2]), "+f"(d[3])
        : "r"(a[0]), "r"(a[1]), "r"(a[2]), "r"(a[3]), "r"(b0), "r"(b1));
}

// ---------------------------------------------------------------------------
// tf32 GEMM: C[128,128] = gather(A)[128,256] @ W[n0:,256]^T + bias
// k-permuted smem: within each 8-word k-group, word kw at (kw&3)*2+(kw>>2).
// Staging: 2x LDG.64 -> 1x STS.128 (conflict-free); frags via LDS.64.
// ---------------------------------------------------------------------------
#define GSM_STRIDE 40
#define GSM_BUF (128 * GSM_STRIDE)
#define GEMM_SMEM (4 * GSM_BUF * 4)     // 81920 bytes

__device__ __forceinline__ void gemm_tc_core(
    const float* __restrict__ A, const int* __restrict__ gidx,
    const float* __restrict__ W, const float* __restrict__ bias,
    float* __restrict__ outp, int m0, int n0, uint32_t* smg)
{
    uint32_t* As = smg;                  // [2][128*40]
    uint32_t* Ws = smg + 2 * GSM_BUF;

    const int tid = threadIdx.x;
    const int rb = tid >> 3;             // 0..31
    const int kq = tid & 7;
    const int gq = kq >> 1, ph = kq & 1;
    const int goff = gq * 8 + 2 * ph;    // gmem float offset within 32-k chunk

    const float* arp[4];
    const float* wrp[4];
    int sofs[4];
#pragma unroll
    for (int l = 0; l < 4; l++) {
        int r = rb + 32 * l;
        arp[l] = A + (size_t)gidx[m0 + r] * 256 + goff;
        wrp[l] = W + (size_t)(n0 + r) * 256 + goff;
        sofs[l] = r * GSM_STRIDE + gq * 8 + 4 * ph;   // uint4 store base
    }

    float2 alo[4], ahi[4], wlo[4], whi[4];
    auto load_regs = [&](int c) {
        const int k0 = c * 32;
#pragma unroll
        for (int l = 0; l < 4; l++) {
            alo[l] = *(const float2*)(arp[l] + k0);
            ahi[l] = *(const float2*)(arp[l] + k0 + 4);
            wlo[l] = *(const float2*)(wrp[l] + k0);
            whi[l] = *(const float2*)(wrp[l] + k0 + 4);
        }
    };
    auto store_smem = [&](int buf) {
        uint32_t* Ab = As + buf * GSM_BUF;
        uint32_t* Wb = Ws + buf * GSM_BUF;
#pragma unroll
        for (int l = 0; l < 4; l++) {
            uint4 va = make_uint4(f2tf32(alo[l].x), f2tf32(ahi[l].x),
                                  f2tf32(alo[l].y), f2tf32(ahi[l].y));
            *(uint4*)(Ab + sofs[l]) = va;
            uint4 vw = make_uint4(f2tf32(wlo[l].x), f2tf32(whi[l].x),
                                  f2tf32(wlo[l].y), f2tf32(whi[l].y));
            *(uint4*)(Wb + sofs[l]) = vw;
        }
    };

    const int warp = tid >> 5, lane = tid & 31;
    const int g = lane >> 2, c = lane & 3;
    const int wm = warp >> 2, wn = warp & 3;
    const int mb = wm * 64, nb = wn * 32;

    float acc[4][4][4];
#pragma unroll
    for (int mi = 0; mi < 4; mi++)
#pragma unroll
        for (int ni = 0; ni < 4; ni++)
#pragma unroll
            for (int t = 0; t < 4; t++) acc[mi][ni][t] = 0.f;

    load_regs(0);
    store_smem(0);
    __syncthreads();

    for (int ch = 0; ch < 8; ch++) {
        if (ch < 7) load_regs(ch + 1);

        const uint32_t* Ab = As + (ch & 1) * GSM_BUF;
        const uint32_t* Wb = Ws + (ch & 1) * GSM_BUF;
#pragma unroll
        for (int kt = 0; kt < 4; kt++) {
            const int kc = kt * 8 + c * 2;
            uint32_t af[4][4];
#pragma unroll
            for (int mi = 0; mi < 4; mi++) {
                const int r = mb + mi * 16 + g;
                uint2 a0 = *(const uint2*)&Ab[r * GSM_STRIDE + kc];
                uint2 a1 = *(const uint2*)&Ab[(r + 8) * GSM_STRIDE + kc];
                af[mi][0] = a0.x; af[mi][1] = a1.x;
                af[mi][2] = a0.y; af[mi][3] = a1.y;
            }
            uint2 bf[4];
#pragma unroll
            for (int ni = 0; ni < 4; ni++)
                bf[ni] = *(const uint2*)&Wb[(nb + ni * 8 + g) * GSM_STRIDE + kc];
#pragma unroll
            for (int mi = 0; mi < 4; mi++)
#pragma unroll
                for (int ni = 0; ni < 4; ni++)
                    mma8(acc[mi][ni], af[mi], bf[ni].x, bf[ni].y);
        }

        if (ch < 7) {
            store_smem((ch + 1) & 1);
            __syncthreads();
        }
    }

    float2 bz[4];
#pragma unroll
    for (int ni = 0; ni < 4; ni++)
        bz[ni] = *(const float2*)&bias[n0 + nb + ni * 8 + 2 * c];

#pragma unroll
    for (int mi = 0; mi < 4; mi++) {
        const int mA = m0 + mb + mi * 16 + g;
        const int mB = mA + 8;
#pragma unroll
        for (int ni = 0; ni < 4; ni++) {
            const int n = n0 + nb + ni * 8 + 2 * c;
            float2 v0 = make_float2(acc[mi][ni][0] + bz[ni].x, acc[mi][ni][1] + bz[ni].y);
            float2 v1 = make_float2(acc[mi][ni][2] + bz[ni].x, acc[mi][ni][3] + bz[ni].y);
            *(float2*)&outp[(size_t)mA * 256 + n] = v0;
            *(float2*)&outp[(size_t)mB * 256 + n] = v1;
        }
    }
}

__global__ __launch_bounds__(256, 2) void gemm_qkv_tc(
    const float* __restrict__ x, const int* __restrict__ pidx,
    const float* __restrict__ Wq, const float* __restrict__ Wk, const float* __restrict__ Wv,
    const float* __restrict__ bq, const float* __restrict__ bk, const float* __restrict__ bv)
{
    extern __shared__ uint32_t smg[];
    const int z = blockIdx.z;
    const float* W  = (z == 0) ? Wq : (z == 1 ? Wk : Wv);
    const float* bi = (z == 0) ? bq : (z == 1 ? bk : bv);
    gemm_tc_core(x, pidx, W, bi, g_qkv + (size_t)z * QKV_ELEMS,
                 blockIdx.x * 128, blockIdx.y * 128, smg);
}

__global__ __launch_bounds__(256, 2) void gemm_proj_tc(
    const int* __restrict__ pinv, const float* __restrict__ Wp,
    const float* __restrict__ bp, float* __restrict__ out)
{
    extern __shared__ uint32_t smg[];
    gemm_tc_core(g_y, pinv, Wp, bp, out, blockIdx.x * 128, blockIdx.y * 128, smg);
}

// ---------------------------------------------------------------------------
// Attention: 256 threads, 8 warps x 64 queries (4 groups of 16).
// Ks [512][40] k-permuted (uint2 B-frags, conflict-free),
// Vs [512][40] identity (scalar B-frags, conflict-free),
// Ps per-warp [16][68] (round-5 proven). Static softmax (no running max):
// scores are O(1); masked -> -50; exp directly; divide by sum at end.
// ---------------------------------------------------------------------------
#define KS_OFF 0
#define VS_OFF (512*40)
#define PS_OFF (VS_OFF + 512*40)
#define SEG_OFF (PS_OFF + 8*1088)
#define ATTN_SMEM ((SEG_OFF + 512) * 4)    // 200704 bytes

__global__ __launch_bounds__(256, 1) void attn_kernel(const int* __restrict__ pbatch)
{
    extern __shared__ uint32_t sm[];
    uint32_t* Ks = sm + KS_OFF;
    uint32_t* Vs = sm + VS_OFF;
    uint32_t* Ps = sm + PS_OFF;
    int*      seg = (int*)(sm + SEG_OFF);

    const int h = blockIdx.x, b = blockIdx.y;
    const float* __restrict__ Qb = g_qkv + (size_t)(b * 512) * 256 + h * 32;
    const float* __restrict__ Kb = Qb + QKV_ELEMS;
    const float* __restrict__ Vb = Qb + 2 * (size_t)QKV_ELEMS;

    const int tid = threadIdx.x;

    // K: permuted staging (2x LDG.64 -> STS.128)
#pragma unroll
    for (int it = 0; it < 16; it++) {
        int idx = tid + it * 256;          // 0..4095
        int j = idx >> 3, sub = idx & 7;
        int gq = sub >> 1, ph2 = sub & 1;
        const float* kr = Kb + (size_t)j * 256 + gq * 8 + 2 * ph2;
        float2 lo = *(const float2*)kr;
        float2 hi = *(const float2*)(kr + 4);
        uint4 v = make_uint4(f2tf32(lo.x), f2tf32(hi.x), f2tf32(lo.y), f2tf32(hi.y));
        *(uint4*)&Ks[j * 40 + gq * 8 + 4 * ph2] = v;
    }
    // V: identity staging
#pragma unroll
    for (int it = 0; it < 16; it++) {
        int idx = tid + it * 256;
        int j = idx >> 3, d4 = idx & 7;
        float4 vv = *(const float4*)(Vb + (size_t)j * 256 + d4 * 4);
        uint4 v = make_uint4(f2tf32(vv.x), f2tf32(vv.y), f2tf32(vv.z), f2tf32(vv.w));
        *(uint4*)&Vs[j * 40 + d4 * 4] = v;
    }
    for (int i = tid; i < 512; i += 256) seg[i] = pbatch[b * 512 + i];
    __syncthreads();

    const int warp = tid >> 5, lane = tid & 31;
    const int g = lane >> 2, c = lane & 3;
    uint32_t* Pw = Ps + warp * 1088;       // [16][68]
    const float scale = 0.17677669529663688f;

    for (int grp = 0; grp < 4; grp++) {
        const int q0 = warp * 64 + grp * 16;
        const int r0 = q0 + g, r1 = q0 + g + 8;
        const float* Q0 = Qb + (size_t)r0 * 256;
        const float* Q1 = Qb + (size_t)r1 * 256;

        uint32_t aq[4][4];
#pragma unroll
        for (int kt = 0; kt < 4; kt++) {
            aq[kt][0] = f2tf32(Q0[kt*8 + c] * scale);
            aq[kt][1] = f2tf32(Q1[kt*8 + c] * scale);
            aq[kt][2] = f2tf32(Q0[kt*8 + c + 4] * scale);
            aq[kt][3] = f2tf32(Q1[kt*8 + c + 4] * scale);
        }
        const int sq0 = seg[r0], sq1 = seg[r1];

        float l0 = 0.f, l1 = 0.f;
        float y[4][4];
#pragma unroll
        for (int n = 0; n < 4; n++)
#pragma unroll
            for (int r = 0; r < 4; r++) y[n][r] = 0.f;

        for (int ch = 0; ch < 8; ch++) {
            const int j0 = ch * 64;
            float s[8][4];
#pragma unroll
            for (int nt = 0; nt < 8; nt++) {
                s[nt][0] = s[nt][1] = s[nt][2] = s[nt][3] = 0.f;
                const int jb = (j0 + nt*8 + g) * 40;
#pragma unroll
                for (int kt = 0; kt < 4; kt++) {
                    uint2 kk = *(const uint2*)&Ks[jb + kt*8 + c*2];
                    mma8(s[nt], aq[kt], kk.x, kk.y);
                }
            }

            // mask + exp (static max) + P store + partial sums
            float ps0 = 0.f, ps1 = 0.f;
#pragma unroll
            for (int nt = 0; nt < 8; nt++) {
                const int jA = j0 + nt*8 + 2*c;
                const int sA = seg[jA], sB = seg[jA + 1];
                float p0 = __expf((sA == sq0) ? -50.f : s[nt][0]);
                float p1 = __expf((sB == sq0) ? -50.f : s[nt][1]);
                float p2 = __expf((sA == sq1) ? -50.f : s[nt][2]);
                float p3 = __expf((sB == sq1) ? -50.f : s[nt][3]);
                ps0 += p0 + p1; ps1 += p2 + p3;
                Pw[g*68      + nt*8 + 2*c    ] = f2tf32(p0);
                Pw[g*68      + nt*8 + 2*c + 1] = f2tf32(p1);
                Pw[(g+8)*68  + nt*8 + 2*c    ] = f2tf32(p2);
                Pw[(g+8)*68  + nt*8 + 2*c + 1] = f2tf32(p3);
            }
            l0 += ps0; l1 += ps1;
            __syncwarp();

            // PV accumulate
#pragma unroll
            for (int kt2 = 0; kt2 < 8; kt2++) {
                uint32_t ap[4];
                ap[0] = Pw[g*68     + kt2*8 + c];
                ap[1] = Pw[(g+8)*68 + kt2*8 + c];
                ap[2] = Pw[g*68     + kt2*8 + c + 4];
                ap[3] = Pw[(g+8)*68 + kt2*8 + c + 4];
                const int vb0 = (j0 + kt2*8 + c) * 40 + g;
                const int vb1 = (j0 + kt2*8 + c + 4) * 40 + g;
#pragma unroll
                for (int nt2 = 0; nt2 < 4; nt2++)
                    mma8(y[nt2], ap, Vs[vb0 + nt2*8], Vs[vb1 + nt2*8]);
            }
            __syncwarp();
        }

        l0 += __shfl_xor_sync(0xffffffffu, l0, 1);
        l0 += __shfl_xor_sync(0xffffffffu, l0, 2);
        l1 += __shfl_xor_sync(0xffffffffu, l1, 1);
        l1 += __shfl_xor_sync(0xffffffffu, l1, 2);
        const float inv0 = 1.0f / l0, inv1 = 1.0f / l1;

        float* O0 = g_y + (size_t)(b * 512 + r0) * 256 + h * 32;
        float* O1 = g_y + (size_t)(b * 512 + r1) * 256 + h * 32;
#pragma unroll
        for (int nt2 = 0; nt2 < 4; nt2++) {
            float2 v0 = make_float2(y[nt2][0] * inv0, y[nt2][1] * inv0);
            float2 v1 = make_float2(y[nt2][2] * inv1, y[nt2][3] * inv1);
            *(float2*)&O0[nt2*8 + 2*c] = v0;
            *(float2*)&O1[nt2*8 + 2*c] = v1;
        }
    }
}

// ---------------------------------------------------------------------------

extern "C" void kernel_launch(void* const* d_in, const int* in_sizes, int n_in,
                              void* d_out, int out_size)
{
    const float* x    = (const float*)d_in[0];
    const float* Wq   = (const float*)d_in[1];
    const float* bq   = (const float*)d_in[2];
    const float* Wk   = (const float*)d_in[3];
    const float* bk   = (const float*)d_in[4];
    const float* Wv   = (const float*)d_in[5];
    const float* bv   = (const float*)d_in[6];
    const float* Wp   = (const float*)d_in[7];
    const float* bp   = (const float*)d_in[8];
    const int* pidx   = (const int*)d_in[9];
    const int* pbatch = (const int*)d_in[10];
    const int* pinv   = (const int*)d_in[11];
    float* out = (float*)d_out;

    cudaFuncSetAttribute(gemm_qkv_tc,  cudaFuncAttributeMaxDynamicSharedMemorySize, GEMM_SMEM);
    cudaFuncSetAttribute(gemm_proj_tc, cudaFuncAttributeMaxDynamicSharedMemorySize, GEMM_SMEM);
    cudaFuncSetAttribute(attn_kernel,  cudaFuncAttributeMaxDynamicSharedMemorySize, ATTN_SMEM);

    gemm_qkv_tc<<<dim3(M_ / 128, 2, 3), 256, GEMM_SMEM>>>(x, pidx, Wq, Wk, Wv, bq, bk, bv);
    attn_kernel<<<dim3(H_, B_), 256, ATTN_SMEM>>>(pbatch);
    gemm_proj_tc<<<dim3(NTOT / 128, 2), 256, GEMM_SMEM>>>(pinv, Wp, bp, out);
}

// round 9
// speedup vs baseline: 1.2847x; 1.0743x over previous
#include <cuda_runtime.h>
#include <cstdint>

#define B_    64
#define T_    512
#define H_    8
#define D_    32
#define C_    256
#define M_    (B_*T_)
#define NTOT  24576
#define QKV_ELEMS (M_*C_)

__device__ float g_qkv[3 * QKV_ELEMS];   // q,k,v each [token][256]
__device__ float g_y[M_ * C_];           // attention out (tf32-rounded)
__device__ float g_xr[NTOT * C_];        // tf32-rounded x
__device__ float g_wr[4 * C_ * C_];      // tf32-rounded Wq,Wk,Wv,Wp

// ---------------- helpers ----------------------------------------------------
__device__ __forceinline__ uint32_t f2tf32(float f) {
    uint32_t u; asm("cvt.rna.tf32.f32 %0, %1;" : "=r"(u) : "f"(f)); return u;
}
__device__ __forceinline__ float rtf(float f) { return __uint_as_float(f2tf32(f)); }
__device__ __forceinline__ void mma8(float* d, const uint32_t* a, uint32_t b0, uint32_t b1) {
    asm volatile(
        "mma.sync.aligned.m16n8k8.row.col.f32.tf32.tf32.f32 "
        "{%0,%1,%2,%3},{%4,%5,%6,%7},{%8,%9},{%0,%1,%2,%3};"
        : "+f"(d[0]), "+f"(d[1]), "+f"(d[2]), "+f"(d[3])
        : "r"(a[0]), "r"(a[1]), "r"(a[2]), "r"(a[3]), "r"(b0), "r"(b1));
}
__device__ __forceinline__ uint32_t smem_u32(const void* p) {
    uint32_t a;
    asm("{ .reg .u64 t; cvta.to.shared.u64 t, %1; cvt.u32.u64 %0, t; }" : "=r"(a) : "l"(p));
    return a;
}
#define CP16(dst, src)  asm volatile("cp.async.cg.shared.global [%0], [%1], 16;" :: "r"(dst), "l"(src))
#define CP_COMMIT()     asm volatile("cp.async.commit_group;" ::: "memory")
#define CP_WAIT1()      asm volatile("cp.async.wait_group 1;" ::: "memory")

// ---------------------------------------------------------------------------
// Pre-rounding pass: x, Wq, Wk, Wv, Wp -> tf32-rounded copies
// ---------------------------------------------------------------------------
__global__ __launch_bounds__(256) void round_inputs(
    const float* __restrict__ x,
    const float* __restrict__ Wq, const float* __restrict__ Wk,
    const float* __restrict__ Wv, const float* __restrict__ Wp)
{
    const int NX4 = (NTOT * C_) / 4;     // 1572864
    const int NW4 = (C_ * C_) / 4;       // 16384
    for (int idx = blockIdx.x * 256 + threadIdx.x; idx < NX4 + 4 * NW4;
         idx += gridDim.x * 256) {
        float4 v; float* dst;
        if (idx < NX4) {
            v = ((const float4*)x)[idx];
            dst = g_xr + (size_t)idx * 4;
        } else {
            int w = idx - NX4, z = w / NW4, o = w - z * NW4;
            const float* src = (z == 0) ? Wq : (z == 1) ? Wk : (z == 2) ? Wv : Wp;
            v = ((const float4*)src)[o];
            dst = g_wr + (size_t)z * 65536 + (size_t)o * 4;
        }
        dst[0] = rtf(v.x); dst[1] = rtf(v.y); dst[2] = rtf(v.z); dst[3] = rtf(v.w);
    }
}

// ---------------------------------------------------------------------------
// tf32 GEMM: C[128,128] = gather(A)[128,256] @ W[n0:,256]^T + bias
// Identity stride-40 smem layout, cp.async staging (raw fp32, pre-rounded),
// contiguous-pair LDS.64 fragments (k-pairs {2c,2c+1} in slots (c,c+4) on
// BOTH operands -> consistent). 2-stage double buffer via commit/wait groups.
// ---------------------------------------------------------------------------
#define GSM_STRIDE 40
#define GSM_BUF (128 * GSM_STRIDE)
#define GEMM_SMEM (4 * GSM_BUF * 4)     // 81920 bytes

__device__ __forceinline__ void gemm_tc_core(
    const float* __restrict__ A, const int* __restrict__ gidx,
    const float* __restrict__ W, const float* __restrict__ bias,
    float* __restrict__ outp, int m0, int n0, uint32_t* smg)
{
    const uint32_t sbase = smem_u32(smg);
    const int tid = threadIdx.x;
    const int rb = tid >> 3, kq = tid & 7;

    const float* asrc[4];
    const float* wsrc[4];
    uint32_t adst[4], wdst[4];
#pragma unroll
    for (int l = 0; l < 4; l++) {
        int r = rb + 32 * l;
        asrc[l] = A + (size_t)gidx[m0 + r] * 256 + kq * 4;
        wsrc[l] = W + (size_t)(n0 + r) * 256 + kq * 4;
        adst[l] = sbase + (r * GSM_STRIDE + kq * 4) * 4;
        wdst[l] = sbase + (2 * GSM_BUF + r * GSM_STRIDE + kq * 4) * 4;
    }

    auto stage = [&](int ch, int buf) {
        const int kof = ch * 32;                 // floats
        const uint32_t bof = buf * GSM_BUF * 4;  // bytes
#pragma unroll
        for (int l = 0; l < 4; l++) CP16(adst[l] + bof, asrc[l] + kof);
#pragma unroll
        for (int l = 0; l < 4; l++) CP16(wdst[l] + bof, wsrc[l] + kof);
    };

    const int warp = tid >> 5, lane = tid & 31;
    const int g = lane >> 2, c = lane & 3;
    const int wm = warp >> 2, wn = warp & 3;
    const int mb = wm * 64, nb = wn * 32;

    float acc[4][4][4];
#pragma unroll
    for (int mi = 0; mi < 4; mi++)
#pragma unroll
        for (int ni = 0; ni < 4; ni++)
#pragma unroll
            for (int t = 0; t < 4; t++) acc[mi][ni][t] = 0.f;

    stage(0, 0); CP_COMMIT();
    stage(1, 1); CP_COMMIT();
    CP_WAIT1(); __syncthreads();                 // buf0 ready

    for (int ch = 0; ch < 8; ch++) {
        const uint32_t* Ab = smg + (ch & 1) * GSM_BUF;
        const uint32_t* Wb = smg + 2 * GSM_BUF + (ch & 1) * GSM_BUF;
#pragma unroll
        for (int kt = 0; kt < 4; kt++) {
            const int kc = kt * 8 + c * 2;
            uint32_t af[4][4];
#pragma unroll
            for (int mi = 0; mi < 4; mi++) {
                const int r = mb + mi * 16 + g;
                uint2 a0 = *(const uint2*)&Ab[r * GSM_STRIDE + kc];
                uint2 a1 = *(const uint2*)&Ab[(r + 8) * GSM_STRIDE + kc];
                af[mi][0] = a0.x; af[mi][1] = a1.x;
                af[mi][2] = a0.y; af[mi][3] = a1.y;
            }
            uint2 bf[4];
#pragma unroll
            for (int ni = 0; ni < 4; ni++)
                bf[ni] = *(const uint2*)&Wb[(nb + ni * 8 + g) * GSM_STRIDE + kc];
#pragma unroll
            for (int mi = 0; mi < 4; mi++)
#pragma unroll
                for (int ni = 0; ni < 4; ni++)
                    mma8(acc[mi][ni], af[mi], bf[ni].x, bf[ni].y);
        }
        __syncthreads();                          // all warps done with buf ch&1
        if (ch < 6) { stage(ch + 2, ch & 1); CP_COMMIT(); }
        if (ch < 7) { CP_WAIT1(); __syncthreads(); }   // buf (ch+1)&1 ready
    }

    float2 bz[4];
#pragma unroll
    for (int ni = 0; ni < 4; ni++)
        bz[ni] = *(const float2*)&bias[n0 + nb + ni * 8 + 2 * c];

#pragma unroll
    for (int mi = 0; mi < 4; mi++) {
        const int mA = m0 + mb + mi * 16 + g;
        const int mB = mA + 8;
#pragma unroll
        for (int ni = 0; ni < 4; ni++) {
            const int n = n0 + nb + ni * 8 + 2 * c;
            float2 v0 = make_float2(acc[mi][ni][0] + bz[ni].x, acc[mi][ni][1] + bz[ni].y);
            float2 v1 = make_float2(acc[mi][ni][2] + bz[ni].x, acc[mi][ni][3] + bz[ni].y);
            *(float2*)&outp[(size_t)mA * 256 + n] = v0;
            *(float2*)&outp[(size_t)mB * 256 + n] = v1;
        }
    }
}

__global__ __launch_bounds__(256, 2) void gemm_qkv_tc(
    const int* __restrict__ pidx,
    const float* __restrict__ bq, const float* __restrict__ bk, const float* __restrict__ bv)
{
    extern __shared__ uint32_t smg[];
    const int z = blockIdx.z;
    const float* bi = (z == 0) ? bq : (z == 1 ? bk : bv);
    gemm_tc_core(g_xr, pidx, g_wr + (size_t)z * 65536, bi,
                 g_qkv + (size_t)z * QKV_ELEMS, blockIdx.x * 128, blockIdx.y * 128, smg);
}

__global__ __launch_bounds__(256, 2) void gemm_proj_tc(
    const int* __restrict__ pinv, const float* __restrict__ bp, float* __restrict__ out)
{
    extern __shared__ uint32_t smg[];
    gemm_tc_core(g_y, pinv, g_wr + 3 * 65536, bp, out,
                 blockIdx.x * 128, blockIdx.y * 128, smg);
}

// ---------------------------------------------------------------------------
// Attention (round-8 proven): 256 threads, 8 warps x 64 queries.
// Epilogue now stores tf32-rounded y (feeds cp.async proj GEMM).
// ---------------------------------------------------------------------------
#define KS_OFF 0
#define VS_OFF (512*40)
#define PS_OFF (VS_OFF + 512*40)
#define SEG_OFF (PS_OFF + 8*1088)
#define ATTN_SMEM ((SEG_OFF + 512) * 4)    // 200704 bytes

__global__ __launch_bounds__(256, 1) void attn_kernel(const int* __restrict__ pbatch)
{
    extern __shared__ uint32_t sm[];
    uint32_t* Ks = sm + KS_OFF;
    uint32_t* Vs = sm + VS_OFF;
    uint32_t* Ps = sm + PS_OFF;
    int*      seg = (int*)(sm + SEG_OFF);

    const int h = blockIdx.x, b = blockIdx.y;
    const float* __restrict__ Qb = g_qkv + (size_t)(b * 512) * 256 + h * 32;
    const float* __restrict__ Kb = Qb + QKV_ELEMS;
    const float* __restrict__ Vb = Qb + 2 * (size_t)QKV_ELEMS;

    const int tid = threadIdx.x;

#pragma unroll
    for (int it = 0; it < 16; it++) {
        int idx = tid + it * 256;
        int j = idx >> 3, sub = idx & 7;
        int gq = sub >> 1, ph2 = sub & 1;
        const float* kr = Kb + (size_t)j * 256 + gq * 8 + 2 * ph2;
        float2 lo = *(const float2*)kr;
        float2 hi = *(const float2*)(kr + 4);
        uint4 v = make_uint4(f2tf32(lo.x), f2tf32(hi.x), f2tf32(lo.y), f2tf32(hi.y));
        *(uint4*)&Ks[j * 40 + gq * 8 + 4 * ph2] = v;
    }
#pragma unroll
    for (int it = 0; it < 16; it++) {
        int idx = tid + it * 256;
        int j = idx >> 3, d4 = idx & 7;
        float4 vv = *(const float4*)(Vb + (size_t)j * 256 + d4 * 4);
        uint4 v = make_uint4(f2tf32(vv.x), f2tf32(vv.y), f2tf32(vv.z), f2tf32(vv.w));
        *(uint4*)&Vs[j * 40 + d4 * 4] = v;
    }
    for (int i = tid; i < 512; i += 256) seg[i] = pbatch[b * 512 + i];
    __syncthreads();

    const int warp = tid >> 5, lane = tid & 31;
    const int g = lane >> 2, c = lane & 3;
    uint32_t* Pw = Ps + warp * 1088;       // [16][68]
    const float scale = 0.17677669529663688f;

    for (int grp = 0; grp < 4; grp++) {
        const int q0 = warp * 64 + grp * 16;
        const int r0 = q0 + g, r1 = q0 + g + 8;
        const float* Q0 = Qb + (size_t)r0 * 256;
        const float* Q1 = Qb + (size_t)r1 * 256;

        uint32_t aq[4][4];
#pragma unroll
        for (int kt = 0; kt < 4; kt++) {
            aq[kt][0] = f2tf32(Q0[kt*8 + c] * scale);
            aq[kt][1] = f2tf32(Q1[kt*8 + c] * scale);
            aq[kt][2] = f2tf32(Q0[kt*8 + c + 4] * scale);
            aq[kt][3] = f2tf32(Q1[kt*8 + c + 4] * scale);
        }
        const int sq0 = seg[r0], sq1 = seg[r1];

        float l0 = 0.f, l1 = 0.f;
        float y[4][4];
#pragma unroll
        for (int n = 0; n < 4; n++)
#pragma unroll
            for (int r = 0; r < 4; r++) y[n][r] = 0.f;

        for (int ch = 0; ch < 8; ch++) {
            const int j0 = ch * 64;
            float s[8][4];
#pragma unroll
            for (int nt = 0; nt < 8; nt++) {
                s[nt][0] = s[nt][1] = s[nt][2] = s[nt][3] = 0.f;
                const int jb = (j0 + nt*8 + g) * 40;
#pragma unroll
                for (int kt = 0; kt < 4; kt++) {
                    uint2 kk = *(const uint2*)&Ks[jb + kt*8 + c*2];
                    mma8(s[nt], aq[kt], kk.x, kk.y);
                }
            }

            float ps0 = 0.f, ps1 = 0.f;
#pragma unroll
            for (int nt = 0; nt < 8; nt++) {
                const int jA = j0 + nt*8 + 2*c;
                const int sA = seg[jA], sB = seg[jA + 1];
                float p0 = __expf((sA == sq0) ? -50.f : s[nt][0]);
                float p1 = __expf((sB == sq0) ? -50.f : s[nt][1]);
                float p2 = __expf((sA == sq1) ? -50.f : s[nt][2]);
                float p3 = __expf((sB == sq1) ? -50.f : s[nt][3]);
                ps0 += p0 + p1; ps1 += p2 + p3;
                Pw[g*68      + nt*8 + 2*c    ] = f2tf32(p0);
                Pw[g*68      + nt*8 + 2*c + 1] = f2tf32(p1);
                Pw[(g+8)*68  + nt*8 + 2*c    ] = f2tf32(p2);
                Pw[(g+8)*68  + nt*8 + 2*c + 1] = f2tf32(p3);
            }
            l0 += ps0; l1 += ps1;
            __syncwarp();

#pragma unroll
            for (int kt2 = 0; kt2 < 8; kt2++) {
                uint32_t ap[4];
                ap[0] = Pw[g*68     + kt2*8 + c];
                ap[1] = Pw[(g+8)*68 + kt2*8 + c];
                ap[2] = Pw[g*68     + kt2*8 + c + 4];
                ap[3] = Pw[(g+8)*68 + kt2*8 + c + 4];
                const int vb0 = (j0 + kt2*8 + c) * 40 + g;
                const int vb1 = (j0 + kt2*8 + c + 4) * 40 + g;
#pragma unroll
                for (int nt2 = 0; nt2 < 4; nt2++)
                    mma8(y[nt2], ap, Vs[vb0 + nt2*8], Vs[vb1 + nt2*8]);
            }
            __syncwarp();
        }

        l0 += __shfl_xor_sync(0xffffffffu, l0, 1);
        l0 += __shfl_xor_sync(0xffffffffu, l0, 2);
        l1 += __shfl_xor_sync(0xffffffffu, l1, 1);
        l1 += __shfl_xor_sync(0xffffffffu, l1, 2);
        const float inv0 = 1.0f / l0, inv1 = 1.0f / l1;

        float* O0 = g_y + (size_t)(b * 512 + r0) * 256 + h * 32;
        float* O1 = g_y + (size_t)(b * 512 + r1) * 256 + h * 32;
#pragma unroll
        for (int nt2 = 0; nt2 < 4; nt2++) {
            float2 v0 = make_float2(rtf(y[nt2][0] * inv0), rtf(y[nt2][1] * inv0));
            float2 v1 = make_float2(rtf(y[nt2][2] * inv1), rtf(y[nt2][3] * inv1));
            *(float2*)&O0[nt2*8 + 2*c] = v0;
            *(float2*)&O1[nt2*8 + 2*c] = v1;
        }
    }
}

// ---------------------------------------------------------------------------

extern "C" void kernel_launch(void* const* d_in, const int* in_sizes, int n_in,
                              void* d_out, int out_size)
{
    const float* x    = (const float*)d_in[0];
    const float* Wq   = (const float*)d_in[1];
    const float* bq   = (const float*)d_in[2];
    const float* Wk   = (const float*)d_in[3];
    const float* bk   = (const float*)d_in[4];
    const float* Wv   = (const float*)d_in[5];
    const float* bv   = (const float*)d_in[6];
    const float* Wp   = (const float*)d_in[7];
    const float* bp   = (const float*)d_in[8];
    const int* pidx   = (const int*)d_in[9];
    const int* pbatch = (const int*)d_in[10];
    const int* pinv   = (const int*)d_in[11];
    float* out = (float*)d_out;

    cudaFuncSetAttribute(gemm_qkv_tc,  cudaFuncAttributeMaxDynamicSharedMemorySize, GEMM_SMEM);
    cudaFuncSetAttribute(gemm_proj_tc, cudaFuncAttributeMaxDynamicSharedMemorySize, GEMM_SMEM);
    cudaFuncSetAttribute(attn_kernel,  cudaFuncAttributeMaxDynamicSharedMemorySize, ATTN_SMEM);

    round_inputs<<<1024, 256>>>(x, Wq, Wk, Wv, Wp);
    gemm_qkv_tc<<<dim3(M_ / 128, 2, 3), 256, GEMM_SMEM>>>(pidx, bq, bk, bv);
    attn_kernel<<<dim3(H_, B_), 256, ATTN_SMEM>>>(pbatch);
    gemm_proj_tc<<<dim3(NTOT / 128, 2), 256, GEMM_SMEM>>>(pinv, bp, out);
}

// round 10
// speedup vs baseline: 1.2926x; 1.0062x over previous
#include <cuda_runtime.h>
#include <cstdint>

#define B_    64
#define T_    512
#define H_    8
#define D_    32
#define C_    256
#define M_    (B_*T_)
#define NTOT  24576
#define QKV_ELEMS (M_*C_)

__device__ float g_qkv[3 * QKV_ELEMS];   // q,k,v each [token][256]
__device__ float g_y[M_ * C_];           // attention out (tf32-rounded)
__device__ float g_xr[NTOT * C_];        // tf32-rounded x
__device__ float g_wr[4 * C_ * C_];      // tf32-rounded Wq,Wk,Wv,Wp

// ---------------- helpers ----------------------------------------------------
__device__ __forceinline__ uint32_t f2tf32(float f) {
    uint32_t u; asm("cvt.rna.tf32.f32 %0, %1;" : "=r"(u) : "f"(f)); return u;
}
__device__ __forceinline__ float rtf(float f) { return __uint_as_float(f2tf32(f)); }
__device__ __forceinline__ void mma8(float* d, const uint32_t* a, uint32_t b0, uint32_t b1) {
    asm volatile(
        "mma.sync.aligned.m16n8k8.row.col.f32.tf32.tf32.f32 "
        "{%0,%1,%2,%3},{%4,%5,%6,%7},{%8,%9},{%0,%1,%2,%3};"
        : "+f"(d[0]), "+f"(d[1]), "+f"(d[2]), "+f"(d[3])
        : "r"(a[0]), "r"(a[1]), "r"(a[2]), "r"(a[3]), "r"(b0), "r"(b1));
}
__device__ __forceinline__ uint32_t smem_u32(const void* p) {
    uint32_t a;
    asm("{ .reg .u64 t; cvta.to.shared.u64 t, %1; cvt.u32.u64 %0, t; }" : "=r"(a) : "l"(p));
    return a;
}
#define CP16(dst, src)  asm volatile("cp.async.cg.shared.global [%0], [%1], 16;" :: "r"(dst), "l"(src))
#define CP_COMMIT()     asm volatile("cp.async.commit_group;" ::: "memory")
#define CP_WAIT1()      asm volatile("cp.async.wait_group 1;" ::: "memory")

// ---------------------------------------------------------------------------
// Pre-rounding pass: x, Wq, Wk, Wv, Wp -> tf32-rounded copies
// ---------------------------------------------------------------------------
__global__ __launch_bounds__(256) void round_inputs(
    const float* __restrict__ x,
    const float* __restrict__ Wq, const float* __restrict__ Wk,
    const float* __restrict__ Wv, const float* __restrict__ Wp)
{
    const int NX4 = (NTOT * C_) / 4;
    const int NW4 = (C_ * C_) / 4;
    for (int idx = blockIdx.x * 256 + threadIdx.x; idx < NX4 + 4 * NW4;
         idx += gridDim.x * 256) {
        float4 v; float* dst;
        if (idx < NX4) {
            v = ((const float4*)x)[idx];
            dst = g_xr + (size_t)idx * 4;
        } else {
            int w = idx - NX4, z = w / NW4, o = w - z * NW4;
            const float* src = (z == 0) ? Wq : (z == 1) ? Wk : (z == 2) ? Wv : Wp;
            v = ((const float4*)src)[o];
            dst = g_wr + (size_t)z * 65536 + (size_t)o * 4;
        }
        dst[0] = rtf(v.x); dst[1] = rtf(v.y); dst[2] = rtf(v.z); dst[3] = rtf(v.w);
    }
}

// ---------------------------------------------------------------------------
// tf32 GEMM: C[128,128] = gather(A)[128,256] @ W[n0:,256]^T + bias
// 128 threads, 4 warps, 64x64 warp tiles (4x8 m16n8k8 grid).
// Identity stride-40 smem, cp.async staging, LDS.64 fragments.
// ---------------------------------------------------------------------------
#define GSM_STRIDE 40
#define GSM_BUF (128 * GSM_STRIDE)
#define GEMM_SMEM (4 * GSM_BUF * 4)     // 81920 bytes

__device__ __forceinline__ void gemm_tc_core(
    const float* __restrict__ A, const int* __restrict__ gidx,
    const float* __restrict__ W, const float* __restrict__ bias,
    float* __restrict__ outp, int m0, int n0, uint32_t* smg)
{
    const uint32_t sbase = smem_u32(smg);
    const int tid = threadIdx.x;
    const int rb = tid >> 3, kq = tid & 7;      // rb 0..15

    // A: 8 gathered row pointers; W/dst: computed from bases (row = rb+16*l)
    const float* asrc[8];
#pragma unroll
    for (int l = 0; l < 8; l++)
        asrc[l] = A + (size_t)gidx[m0 + rb + 16 * l] * 256 + kq * 4;
    const float* wbase = W + (size_t)(n0 + rb) * 256 + kq * 4;
    const uint32_t adst0 = sbase + (rb * GSM_STRIDE + kq * 4) * 4;
    const uint32_t wdst0 = adst0 + 2 * GSM_BUF * 4;

    auto stage = [&](int ch, int buf) {
        const int kof = ch * 32;
        const uint32_t bof = buf * GSM_BUF * 4;
#pragma unroll
        for (int l = 0; l < 8; l++)
            CP16(adst0 + bof + l * (16 * GSM_STRIDE * 4), asrc[l] + kof);
#pragma unroll
        for (int l = 0; l < 8; l++)
            CP16(wdst0 + bof + l * (16 * GSM_STRIDE * 4), wbase + kof + l * 4096);
    };

    const int warp = tid >> 5, lane = tid & 31;
    const int g = lane >> 2, c = lane & 3;
    const int wm = warp >> 1, wn = warp & 1;
    const int mb = wm * 64, nb = wn * 64;

    float acc[4][8][4];
#pragma unroll
    for (int mi = 0; mi < 4; mi++)
#pragma unroll
        for (int ni = 0; ni < 8; ni++)
#pragma unroll
            for (int t = 0; t < 4; t++) acc[mi][ni][t] = 0.f;

    stage(0, 0); CP_COMMIT();
    stage(1, 1); CP_COMMIT();
    CP_WAIT1(); __syncthreads();

    for (int ch = 0; ch < 8; ch++) {
        const uint32_t* Ab = smg + (ch & 1) * GSM_BUF;
        const uint32_t* Wb = smg + 2 * GSM_BUF + (ch & 1) * GSM_BUF;
#pragma unroll
        for (int kt = 0; kt < 4; kt++) {
            const int kc = kt * 8 + c * 2;
            uint32_t af[4][4];
#pragma unroll
            for (int mi = 0; mi < 4; mi++) {
                const int r = mb + mi * 16 + g;
                uint2 a0 = *(const uint2*)&Ab[r * GSM_STRIDE + kc];
                uint2 a1 = *(const uint2*)&Ab[(r + 8) * GSM_STRIDE + kc];
                af[mi][0] = a0.x; af[mi][1] = a1.x;
                af[mi][2] = a0.y; af[mi][3] = a1.y;
            }
            uint2 bf[8];
#pragma unroll
            for (int ni = 0; ni < 8; ni++)
                bf[ni] = *(const uint2*)&Wb[(nb + ni * 8 + g) * GSM_STRIDE + kc];
#pragma unroll
            for (int mi = 0; mi < 4; mi++)
#pragma unroll
                for (int ni = 0; ni < 8; ni++)
                    mma8(acc[mi][ni], af[mi], bf[ni].x, bf[ni].y);
        }
        __syncthreads();
        if (ch < 6) { stage(ch + 2, ch & 1); CP_COMMIT(); }
        if (ch < 7) { CP_WAIT1(); __syncthreads(); }
    }

    float2 bz[8];
#pragma unroll
    for (int ni = 0; ni < 8; ni++)
        bz[ni] = *(const float2*)&bias[n0 + nb + ni * 8 + 2 * c];

#pragma unroll
    for (int mi = 0; mi < 4; mi++) {
        const int mA = m0 + mb + mi * 16 + g;
        const int mB = mA + 8;
#pragma unroll
        for (int ni = 0; ni < 8; ni++) {
            const int n = n0 + nb + ni * 8 + 2 * c;
            float2 v0 = make_float2(acc[mi][ni][0] + bz[ni].x, acc[mi][ni][1] + bz[ni].y);
            float2 v1 = make_float2(acc[mi][ni][2] + bz[ni].x, acc[mi][ni][3] + bz[ni].y);
            *(float2*)&outp[(size_t)mA * 256 + n] = v0;
            *(float2*)&outp[(size_t)mB * 256 + n] = v1;
        }
    }
}

__global__ __launch_bounds__(128, 2) void gemm_qkv_tc(
    const int* __restrict__ pidx,
    const float* __restrict__ bq, const float* __restrict__ bk, const float* __restrict__ bv)
{
    extern __shared__ uint32_t smg[];
    const int z = blockIdx.z;
    const float* bi = (z == 0) ? bq : (z == 1 ? bk : bv);
    gemm_tc_core(g_xr, pidx, g_wr + (size_t)z * 65536, bi,
                 g_qkv + (size_t)z * QKV_ELEMS, blockIdx.x * 128, blockIdx.y * 128, smg);
}

__global__ __launch_bounds__(128, 2) void gemm_proj_tc(
    const int* __restrict__ pinv, const float* __restrict__ bp, float* __restrict__ out)
{
    extern __shared__ uint32_t smg[];
    gemm_tc_core(g_y, pinv, g_wr + 3 * 65536, bp, out,
                 blockIdx.x * 128, blockIdx.y * 128, smg);
}

// ---------------------------------------------------------------------------
// Attention (round-9 proven, unchanged)
// ---------------------------------------------------------------------------
#define KS_OFF 0
#define VS_OFF (512*40)
#define PS_OFF (VS_OFF + 512*40)
#define SEG_OFF (PS_OFF + 8*1088)
#define ATTN_SMEM ((SEG_OFF + 512) * 4)    // 200704 bytes

__global__ __launch_bounds__(256, 1) void attn_kernel(const int* __restrict__ pbatch)
{
    extern __shared__ uint32_t sm[];
    uint32_t* Ks = sm + KS_OFF;
    uint32_t* Vs = sm + VS_OFF;
    uint32_t* Ps = sm + PS_OFF;
    int*      seg = (int*)(sm + SEG_OFF);

    const int h = blockIdx.x, b = blockIdx.y;
    const float* __restrict__ Qb = g_qkv + (size_t)(b * 512) * 256 + h * 32;
    const float* __restrict__ Kb = Qb + QKV_ELEMS;
    const float* __restrict__ Vb = Qb + 2 * (size_t)QKV_ELEMS;

    const int tid = threadIdx.x;

#pragma unroll
    for (int it = 0; it < 16; it++) {
        int idx = tid + it * 256;
        int j = idx >> 3, sub = idx & 7;
        int gq = sub >> 1, ph2 = sub & 1;
        const float* kr = Kb + (size_t)j * 256 + gq * 8 + 2 * ph2;
        float2 lo = *(const float2*)kr;
        float2 hi = *(const float2*)(kr + 4);
        uint4 v = make_uint4(f2tf32(lo.x), f2tf32(hi.x), f2tf32(lo.y), f2tf32(hi.y));
        *(uint4*)&Ks[j * 40 + gq * 8 + 4 * ph2] = v;
    }
#pragma unroll
    for (int it = 0; it < 16; it++) {
        int idx = tid + it * 256;
        int j = idx >> 3, d4 = idx & 7;
        float4 vv = *(const float4*)(Vb + (size_t)j * 256 + d4 * 4);
        uint4 v = make_uint4(f2tf32(vv.x), f2tf32(vv.y), f2tf32(vv.z), f2tf32(vv.w));
        *(uint4*)&Vs[j * 40 + d4 * 4] = v;
    }
    for (int i = tid; i < 512; i += 256) seg[i] = pbatch[b * 512 + i];
    __syncthreads();

    const int warp = tid >> 5, lane = tid & 31;
    const int g = lane >> 2, c = lane & 3;
    uint32_t* Pw = Ps + warp * 1088;       // [16][68]
    const float scale = 0.17677669529663688f;

    for (int grp = 0; grp < 4; grp++) {
        const int q0 = warp * 64 + grp * 16;
        const int r0 = q0 + g, r1 = q0 + g + 8;
        const float* Q0 = Qb + (size_t)r0 * 256;
        const float* Q1 = Qb + (size_t)r1 * 256;

        uint32_t aq[4][4];
#pragma unroll
        for (int kt = 0; kt < 4; kt++) {
            aq[kt][0] = f2tf32(Q0[kt*8 + c] * scale);
            aq[kt][1] = f2tf32(Q1[kt*8 + c] * scale);
            aq[kt][2] = f2tf32(Q0[kt*8 + c + 4] * scale);
            aq[kt][3] = f2tf32(Q1[kt*8 + c + 4] * scale);
        }
        const int sq0 = seg[r0], sq1 = seg[r1];

        float l0 = 0.f, l1 = 0.f;
        float y[4][4];
#pragma unroll
        for (int n = 0; n < 4; n++)
#pragma unroll
            for (int r = 0; r < 4; r++) y[n][r] = 0.f;

        for (int ch = 0; ch < 8; ch++) {
            const int j0 = ch * 64;
            float s[8][4];
#pragma unroll
            for (int nt = 0; nt < 8; nt++) {
                s[nt][0] = s[nt][1] = s[nt][2] = s[nt][3] = 0.f;
                const int jb = (j0 + nt*8 + g) * 40;
#pragma unroll
                for (int kt = 0; kt < 4; kt++) {
                    uint2 kk = *(const uint2*)&Ks[jb + kt*8 + c*2];
                    mma8(s[nt], aq[kt], kk.x, kk.y);
                }
            }

            float ps0 = 0.f, ps1 = 0.f;
#pragma unroll
            for (int nt = 0; nt < 8; nt++) {
                const int jA = j0 + nt*8 + 2*c;
                const int sA = seg[jA], sB = seg[jA + 1];
                float p0 = __expf((sA == sq0) ? -50.f : s[nt][0]);
                float p1 = __expf((sB == sq0) ? -50.f : s[nt][1]);
                float p2 = __expf((sA == sq1) ? -50.f : s[nt][2]);
                float p3 = __expf((sB == sq1) ? -50.f : s[nt][3]);
                ps0 += p0 + p1; ps1 += p2 + p3;
                Pw[g*68      + nt*8 + 2*c    ] = f2tf32(p0);
                Pw[g*68      + nt*8 + 2*c + 1] = f2tf32(p1);
                Pw[(g+8)*68  + nt*8 + 2*c    ] = f2tf32(p2);
                Pw[(g+8)*68  + nt*8 + 2*c + 1] = f2tf32(p3);
            }
            l0 += ps0; l1 += ps1;
            __syncwarp();

#pragma unroll
            for (int kt2 = 0; kt2 < 8; kt2++) {
                uint32_t ap[4];
                ap[0] = Pw[g*68     + kt2*8 + c];
                ap[1] = Pw[(g+8)*68 + kt2*8 + c];
                ap[2] = Pw[g*68     + kt2*8 + c + 4];
                ap[3] = Pw[(g+8)*68 + kt2*8 + c + 4];
                const int vb0 = (j0 + kt2*8 + c) * 40 + g;
                const int vb1 = (j0 + kt2*8 + c + 4) * 40 + g;
#pragma unroll
                for (int nt2 = 0; nt2 < 4; nt2++)
                    mma8(y[nt2], ap, Vs[vb0 + nt2*8], Vs[vb1 + nt2*8]);
            }
            __syncwarp();
        }

        l0 += __shfl_xor_sync(0xffffffffu, l0, 1);
        l0 += __shfl_xor_sync(0xffffffffu, l0, 2);
        l1 += __shfl_xor_sync(0xffffffffu, l1, 1);
        l1 += __shfl_xor_sync(0xffffffffu, l1, 2);
        const float inv0 = 1.0f / l0, inv1 = 1.0f / l1;

        float* O0 = g_y + (size_t)(b * 512 + r0) * 256 + h * 32;
        float* O1 = g_y + (size_t)(b * 512 + r1) * 256 + h * 32;
#pragma unroll
        for (int nt2 = 0; nt2 < 4; nt2++) {
            float2 v0 = make_float2(rtf(y[nt2][0] * inv0), rtf(y[nt2][1] * inv0));
            float2 v1 = make_float2(rtf(y[nt2][2] * inv1), rtf(y[nt2][3] * inv1));
            *(float2*)&O0[nt2*8 + 2*c] = v0;
            *(float2*)&O1[nt2*8 + 2*c] = v1;
        }
    }
}

// ---------------------------------------------------------------------------

extern "C" void kernel_launch(void* const* d_in, const int* in_sizes, int n_in,
                              void* d_out, int out_size)
{
    const float* x    = (const float*)d_in[0];
    const float* Wq   = (const float*)d_in[1];
    const float* bq   = (const float*)d_in[2];
    const float* Wk   = (const float*)d_in[3];
    const float* bk   = (const float*)d_in[4];
    const float* Wv   = (const float*)d_in[5];
    const float* bv   = (const float*)d_in[6];
    const float* Wp   = (const float*)d_in[7];
    const float* bp   = (const float*)d_in[8];
    const int* pidx   = (const int*)d_in[9];
    const int* pbatch = (const int*)d_in[10];
    const int* pinv   = (const int*)d_in[11];
    float* out = (float*)d_out;

    cudaFuncSetAttribute(gemm_qkv_tc,  cudaFuncAttributeMaxDynamicSharedMemorySize, GEMM_SMEM);
    cudaFuncSetAttribute(gemm_proj_tc, cudaFuncAttributeMaxDynamicSharedMemorySize, GEMM_SMEM);
    cudaFuncSetAttribute(attn_kernel,  cudaFuncAttributeMaxDynamicSharedMemorySize, ATTN_SMEM);

    round_inputs<<<1024, 256>>>(x, Wq, Wk, Wv, Wp);
    gemm_qkv_tc<<<dim3(M_ / 128, 2, 3), 128, GEMM_SMEM>>>(pidx, bq, bk, bv);
    attn_kernel<<<dim3(H_, B_), 256, ATTN_SMEM>>>(pbatch);
    gemm_proj_tc<<<dim3(NTOT / 128, 2), 128, GEMM_SMEM>>>(pinv, bp, out);
}

// round 11
// speedup vs baseline: 1.3580x; 1.0506x over previous
#include <cuda_runtime.h>
#include <cstdint>

#define B_    64
#define T_    512
#define H_    8
#define D_    32
#define C_    256
#define M_    (B_*T_)
#define NTOT  24576
#define QKV_ELEMS (M_*C_)

__device__ float g_qkv[3 * QKV_ELEMS];   // q,k,v each [token][256]
__device__ float g_y[M_ * C_];           // attention out (tf32-rounded)
__device__ float g_xr[NTOT * C_];        // tf32-rounded x
__device__ float g_wr[4 * C_ * C_];      // tf32-rounded Wq,Wk,Wv,Wp

// ---------------- helpers ----------------------------------------------------
__device__ __forceinline__ uint32_t f2tf32(float f) {
    uint32_t u; asm("cvt.rna.tf32.f32 %0, %1;" : "=r"(u) : "f"(f)); return u;
}
__device__ __forceinline__ float rtf(float f) { return __uint_as_float(f2tf32(f)); }
__device__ __forceinline__ float ex2f(float x) {
    float y; asm("ex2.approx.f32 %0, %1;" : "=f"(y) : "f"(x)); return y;
}
__device__ __forceinline__ void mma8(float* d, const uint32_t* a, uint32_t b0, uint32_t b1) {
    asm volatile(
        "mma.sync.aligned.m16n8k8.row.col.f32.tf32.tf32.f32 "
        "{%0,%1,%2,%3},{%4,%5,%6,%7},{%8,%9},{%0,%1,%2,%3};"
        : "+f"(d[0]), "+f"(d[1]), "+f"(d[2]), "+f"(d[3])
        : "r"(a[0]), "r"(a[1]), "r"(a[2]), "r"(a[3]), "r"(b0), "r"(b1));
}
__device__ __forceinline__ uint32_t smem_u32(const void* p) {
    uint32_t a;
    asm("{ .reg .u64 t; cvta.to.shared.u64 t, %1; cvt.u32.u64 %0, t; }" : "=r"(a) : "l"(p));
    return a;
}
#define CP16(dst, src)  asm volatile("cp.async.cg.shared.global [%0], [%1], 16;" :: "r"(dst), "l"(src))
#define CP_COMMIT()     asm volatile("cp.async.commit_group;" ::: "memory")
#define CP_WAIT1()      asm volatile("cp.async.wait_group 1;" ::: "memory")

// ---------------------------------------------------------------------------
// Pre-rounding pass
// ---------------------------------------------------------------------------
__global__ __launch_bounds__(256) void round_inputs(
    const float* __restrict__ x,
    const float* __restrict__ Wq, const float* __restrict__ Wk,
    const float* __restrict__ Wv, const float* __restrict__ Wp)
{
    const int NX4 = (NTOT * C_) / 4;
    const int NW4 = (C_ * C_) / 4;
    for (int idx = blockIdx.x * 256 + threadIdx.x; idx < NX4 + 4 * NW4;
         idx += gridDim.x * 256) {
        float4 v; float* dst;
        if (idx < NX4) {
            v = ((const float4*)x)[idx];
            dst = g_xr + (size_t)idx * 4;
        } else {
            int w = idx - NX4, z = w / NW4, o = w - z * NW4;
            const float* src = (z == 0) ? Wq : (z == 1) ? Wk : (z == 2) ? Wv : Wp;
            v = ((const float4*)src)[o];
            dst = g_wr + (size_t)z * 65536 + (size_t)o * 4;
        }
        dst[0] = rtf(v.x); dst[1] = rtf(v.y); dst[2] = rtf(v.z); dst[3] = rtf(v.w);
    }
}

// ---------------------------------------------------------------------------
// tf32 GEMM (round-10 proven, unchanged): 128 thr, 4 warps, 64x64 warp tiles
// ---------------------------------------------------------------------------
#define GSM_STRIDE 40
#define GSM_BUF (128 * GSM_STRIDE)
#define GEMM_SMEM (4 * GSM_BUF * 4)     // 81920 bytes

__device__ __forceinline__ void gemm_tc_core(
    const float* __restrict__ A, const int* __restrict__ gidx,
    const float* __restrict__ W, const float* __restrict__ bias,
    float* __restrict__ outp, int m0, int n0, uint32_t* smg)
{
    const uint32_t sbase = smem_u32(smg);
    const int tid = threadIdx.x;
    const int rb = tid >> 3, kq = tid & 7;

    const float* asrc[8];
#pragma unroll
    for (int l = 0; l < 8; l++)
        asrc[l] = A + (size_t)gidx[m0 + rb + 16 * l] * 256 + kq * 4;
    const float* wbase = W + (size_t)(n0 + rb) * 256 + kq * 4;
    const uint32_t adst0 = sbase + (rb * GSM_STRIDE + kq * 4) * 4;
    const uint32_t wdst0 = adst0 + 2 * GSM_BUF * 4;

    auto stage = [&](int ch, int buf) {
        const int kof = ch * 32;
        const uint32_t bof = buf * GSM_BUF * 4;
#pragma unroll
        for (int l = 0; l < 8; l++)
            CP16(adst0 + bof + l * (16 * GSM_STRIDE * 4), asrc[l] + kof);
#pragma unroll
        for (int l = 0; l < 8; l++)
            CP16(wdst0 + bof + l * (16 * GSM_STRIDE * 4), wbase + kof + l * 4096);
    };

    const int warp = tid >> 5, lane = tid & 31;
    const int g = lane >> 2, c = lane & 3;
    const int wm = warp >> 1, wn = warp & 1;
    const int mb = wm * 64, nb = wn * 64;

    float acc[4][8][4];
#pragma unroll
    for (int mi = 0; mi < 4; mi++)
#pragma unroll
        for (int ni = 0; ni < 8; ni++)
#pragma unroll
            for (int t = 0; t < 4; t++) acc[mi][ni][t] = 0.f;

    stage(0, 0); CP_COMMIT();
    stage(1, 1); CP_COMMIT();
    CP_WAIT1(); __syncthreads();

    for (int ch = 0; ch < 8; ch++) {
        const uint32_t* Ab = smg + (ch & 1) * GSM_BUF;
        const uint32_t* Wb = smg + 2 * GSM_BUF + (ch & 1) * GSM_BUF;
#pragma unroll
        for (int kt = 0; kt < 4; kt++) {
            const int kc = kt * 8 + c * 2;
            uint32_t af[4][4];
#pragma unroll
            for (int mi = 0; mi < 4; mi++) {
                const int r = mb + mi * 16 + g;
                uint2 a0 = *(const uint2*)&Ab[r * GSM_STRIDE + kc];
                uint2 a1 = *(const uint2*)&Ab[(r + 8) * GSM_STRIDE + kc];
                af[mi][0] = a0.x; af[mi][1] = a1.x;
                af[mi][2] = a0.y; af[mi][3] = a1.y;
            }
            uint2 bf[8];
#pragma unroll
            for (int ni = 0; ni < 8; ni++)
                bf[ni] = *(const uint2*)&Wb[(nb + ni * 8 + g) * GSM_STRIDE + kc];
#pragma unroll
            for (int mi = 0; mi < 4; mi++)
#pragma unroll
                for (int ni = 0; ni < 8; ni++)
                    mma8(acc[mi][ni], af[mi], bf[ni].x, bf[ni].y);
        }
        __syncthreads();
        if (ch < 6) { stage(ch + 2, ch & 1); CP_COMMIT(); }
        if (ch < 7) { CP_WAIT1(); __syncthreads(); }
    }

    float2 bz[8];
#pragma unroll
    for (int ni = 0; ni < 8; ni++)
        bz[ni] = *(const float2*)&bias[n0 + nb + ni * 8 + 2 * c];

#pragma unroll
    for (int mi = 0; mi < 4; mi++) {
        const int mA = m0 + mb + mi * 16 + g;
        const int mB = mA + 8;
#pragma unroll
        for (int ni = 0; ni < 8; ni++) {
            const int n = n0 + nb + ni * 8 + 2 * c;
            float2 v0 = make_float2(acc[mi][ni][0] + bz[ni].x, acc[mi][ni][1] + bz[ni].y);
            float2 v1 = make_float2(acc[mi][ni][2] + bz[ni].x, acc[mi][ni][3] + bz[ni].y);
            *(float2*)&outp[(size_t)mA * 256 + n] = v0;
            *(float2*)&outp[(size_t)mB * 256 + n] = v1;
        }
    }
}

__global__ __launch_bounds__(128, 2) void gemm_qkv_tc(
    const int* __restrict__ pidx,
    const float* __restrict__ bq, const float* __restrict__ bk, const float* __restrict__ bv)
{
    extern __shared__ uint32_t smg[];
    const int z = blockIdx.z;
    const float* bi = (z == 0) ? bq : (z == 1 ? bk : bv);
    gemm_tc_core(g_xr, pidx, g_wr + (size_t)z * 65536, bi,
                 g_qkv + (size_t)z * QKV_ELEMS, blockIdx.x * 128, blockIdx.y * 128, smg);
}

__global__ __launch_bounds__(128, 2) void gemm_proj_tc(
    const int* __restrict__ pinv, const float* __restrict__ bp, float* __restrict__ out)
{
    extern __shared__ uint32_t smg[];
    gemm_tc_core(g_y, pinv, g_wr + 3 * 65536, bp, out,
                 blockIdx.x * 128, blockIdx.y * 128, smg);
}

// ---------------------------------------------------------------------------
// Attention: 256 threads, 8 warps x 64 queries (4 groups of 16).
// j-chunks widened to 128 (4 iterations): 64 back-to-back QK MMAs and
// 64 batched exps per chunk; PV in two 64-j halves through the per-warp
// P buffer [16][68]. exp2-based softmax (log2e folded into Q scale).
// ---------------------------------------------------------------------------
#define KS_OFF 0
#define VS_OFF (512*40)
#define PS_OFF (VS_OFF + 512*40)
#define SEG_OFF (PS_OFF + 8*1088)
#define ATTN_SMEM ((SEG_OFF + 512) * 4)    // 200704 bytes

__global__ __launch_bounds__(256, 1) void attn_kernel(const int* __restrict__ pbatch)
{
    extern __shared__ uint32_t sm[];
    uint32_t* Ks = sm + KS_OFF;
    uint32_t* Vs = sm + VS_OFF;
    uint32_t* Ps = sm + PS_OFF;
    int*      seg = (int*)(sm + SEG_OFF);

    const int h = blockIdx.x, b = blockIdx.y;
    const float* __restrict__ Qb = g_qkv + (size_t)(b * 512) * 256 + h * 32;
    const float* __restrict__ Kb = Qb + QKV_ELEMS;
    const float* __restrict__ Vb = Qb + 2 * (size_t)QKV_ELEMS;

    const int tid = threadIdx.x;

#pragma unroll
    for (int it = 0; it < 16; it++) {
        int idx = tid + it * 256;
        int j = idx >> 3, sub = idx & 7;
        int gq = sub >> 1, ph2 = sub & 1;
        const float* kr = Kb + (size_t)j * 256 + gq * 8 + 2 * ph2;
        float2 lo = *(const float2*)kr;
        float2 hi = *(const float2*)(kr + 4);
        uint4 v = make_uint4(f2tf32(lo.x), f2tf32(hi.x), f2tf32(lo.y), f2tf32(hi.y));
        *(uint4*)&Ks[j * 40 + gq * 8 + 4 * ph2] = v;
    }
#pragma unroll
    for (int it = 0; it < 16; it++) {
        int idx = tid + it * 256;
        int j = idx >> 3, d4 = idx & 7;
        float4 vv = *(const float4*)(Vb + (size_t)j * 256 + d4 * 4);
        uint4 v = make_uint4(f2tf32(vv.x), f2tf32(vv.y), f2tf32(vv.z), f2tf32(vv.w));
        *(uint4*)&Vs[j * 40 + d4 * 4] = v;
    }
    for (int i = tid; i < 512; i += 256) seg[i] = pbatch[b * 512 + i];
    __syncthreads();

    const int warp = tid >> 5, lane = tid & 31;
    const int g = lane >> 2, c = lane & 3;
    uint32_t* Pw = Ps + warp * 1088;       // [16][68]
    const float scale = 0.17677669529663688f * 1.4426950408889634f; // 1/sqrt(32)*log2e

    for (int grp = 0; grp < 4; grp++) {
        const int q0 = warp * 64 + grp * 16;
        const int r0 = q0 + g, r1 = q0 + g + 8;
        const float* Q0 = Qb + (size_t)r0 * 256;
        const float* Q1 = Qb + (size_t)r1 * 256;

        uint32_t aq[4][4];
#pragma unroll
        for (int kt = 0; kt < 4; kt++) {
            aq[kt][0] = f2tf32(Q0[kt*8 + c] * scale);
            aq[kt][1] = f2tf32(Q1[kt*8 + c] * scale);
            aq[kt][2] = f2tf32(Q0[kt*8 + c + 4] * scale);
            aq[kt][3] = f2tf32(Q1[kt*8 + c + 4] * scale);
        }
        const int sq0 = seg[r0], sq1 = seg[r1];

        float l0 = 0.f, l1 = 0.f;
        float y[4][4];
#pragma unroll
        for (int n = 0; n < 4; n++)
#pragma unroll
            for (int r = 0; r < 4; r++) y[n][r] = 0.f;

        for (int ch = 0; ch < 4; ch++) {           // 128-wide j chunks
            const int j0 = ch * 128;
            float s[16][4];
            // ---- QK: 64 independent MMAs ----
#pragma unroll
            for (int nt = 0; nt < 16; nt++) {
                s[nt][0] = s[nt][1] = s[nt][2] = s[nt][3] = 0.f;
                const int jb = (j0 + nt*8 + g) * 40;
#pragma unroll
                for (int kt = 0; kt < 4; kt++) {
                    uint2 kk = *(const uint2*)&Ks[jb + kt*8 + c*2];
                    mma8(s[nt], aq[kt], kk.x, kk.y);
                }
            }
            // ---- mask + exp2 (batched, 64 per query-row pair) ----
            float ps0 = 0.f, ps1 = 0.f;
#pragma unroll
            for (int nt = 0; nt < 16; nt++) {
                int2 sp = *(const int2*)&seg[j0 + nt*8 + 2*c];
                float p0 = ex2f((sp.x == sq0) ? -72.f : s[nt][0]);
                float p1 = ex2f((sp.y == sq0) ? -72.f : s[nt][1]);
                float p2 = ex2f((sp.x == sq1) ? -72.f : s[nt][2]);
                float p3 = ex2f((sp.y == sq1) ? -72.f : s[nt][3]);
                s[nt][0] = p0; s[nt][1] = p1; s[nt][2] = p2; s[nt][3] = p3;
                ps0 += p0 + p1; ps1 += p2 + p3;
            }
            l0 += ps0; l1 += ps1;

            // ---- PV in two 64-j halves through Pw ----
#pragma unroll
            for (int hf = 0; hf < 2; hf++) {
                __syncwarp();
#pragma unroll
                for (int nt2 = 0; nt2 < 8; nt2++) {
                    const int nt = hf * 8 + nt2;
                    Pw[g*68      + nt2*8 + 2*c    ] = f2tf32(s[nt][0]);
                    Pw[g*68      + nt2*8 + 2*c + 1] = f2tf32(s[nt][1]);
                    Pw[(g+8)*68  + nt2*8 + 2*c    ] = f2tf32(s[nt][2]);
                    Pw[(g+8)*68  + nt2*8 + 2*c + 1] = f2tf32(s[nt][3]);
                }
                __syncwarp();
                const int jh = j0 + hf * 64;
#pragma unroll
                for (int kt2 = 0; kt2 < 8; kt2++) {
                    uint32_t ap[4];
                    ap[0] = Pw[g*68     + kt2*8 + c];
                    ap[1] = Pw[(g+8)*68 + kt2*8 + c];
                    ap[2] = Pw[g*68     + kt2*8 + c + 4];
                    ap[3] = Pw[(g+8)*68 + kt2*8 + c + 4];
                    const int vb0 = (jh + kt2*8 + c) * 40 + g;
                    const int vb1 = (jh + kt2*8 + c + 4) * 40 + g;
#pragma unroll
                    for (int nt2 = 0; nt2 < 4; nt2++)
                        mma8(y[nt2], ap, Vs[vb0 + nt2*8], Vs[vb1 + nt2*8]);
                }
            }
        }

        l0 += __shfl_xor_sync(0xffffffffu, l0, 1);
        l0 += __shfl_xor_sync(0xffffffffu, l0, 2);
        l1 += __shfl_xor_sync(0xffffffffu, l1, 1);
        l1 += __shfl_xor_sync(0xffffffffu, l1, 2);
        const float inv0 = 1.0f / l0, inv1 = 1.0f / l1;

        float* O0 = g_y + (size_t)(b * 512 + r0) * 256 + h * 32;
        float* O1 = g_y + (size_t)(b * 512 + r1) * 256 + h * 32;
#pragma unroll
        for (int nt2 = 0; nt2 < 4; nt2++) {
            float2 v0 = make_float2(rtf(y[nt2][0] * inv0), rtf(y[nt2][1] * inv0));
            float2 v1 = make_float2(rtf(y[nt2][2] * inv1), rtf(y[nt2][3] * inv1));
            *(float2*)&O0[nt2*8 + 2*c] = v0;
            *(float2*)&O1[nt2*8 + 2*c] = v1;
        }
    }
}

// ---------------------------------------------------------------------------

extern "C" void kernel_launch(void* const* d_in, const int* in_sizes, int n_in,
                              void* d_out, int out_size)
{
    const float* x    = (const float*)d_in[0];
    const float* Wq   = (const float*)d_in[1];
    const float* bq   = (const float*)d_in[2];
    const float* Wk   = (const float*)d_in[3];
    const float* bk   = (const float*)d_in[4];
    const float* Wv   = (const float*)d_in[5];
    const float* bv   = (const float*)d_in[6];
    const float* Wp   = (const float*)d_in[7];
    const float* bp   = (const float*)d_in[8];
    const int* pidx   = (const int*)d_in[9];
    const int* pbatch = (const int*)d_in[10];
    const int* pinv   = (const int*)d_in[11];
    float* out = (float*)d_out;

    cudaFuncSetAttribute(gemm_qkv_tc,  cudaFuncAttributeMaxDynamicSharedMemorySize, GEMM_SMEM);
    cudaFuncSetAttribute(gemm_proj_tc, cudaFuncAttributeMaxDynamicSharedMemorySize, GEMM_SMEM);
    cudaFuncSetAttribute(attn_kernel,  cudaFuncAttributeMaxDynamicSharedMemorySize, ATTN_SMEM);

    round_inputs<<<1024, 256>>>(x, Wq, Wk, Wv, Wp);
    gemm_qkv_tc<<<dim3(M_ / 128, 2, 3), 128, GEMM_SMEM>>>(pidx, bq, bk, bv);
    attn_kernel<<<dim3(H_, B_), 256, ATTN_SMEM>>>(pbatch);
    gemm_proj_tc<<<dim3(NTOT / 128, 2), 128, GEMM_SMEM>>>(pinv, bp, out);
}

// round 12
// speedup vs baseline: 1.4124x; 1.0401x over previous
#include <cuda_runtime.h>
#include <cstdint>

#define B_    64
#define T_    512
#define H_    8
#define D_    32
#define C_    256
#define M_    (B_*T_)
#define NTOT  24576
#define QKV_ELEMS (M_*C_)

__device__ float g_qkv[3 * QKV_ELEMS];   // q,k,v each [token][256]
__device__ float g_y[M_ * C_];           // attention out (tf32-rounded)
__device__ float g_xr[NTOT * C_];        // tf32-rounded x
__device__ float g_wr[4 * C_ * C_];      // tf32-rounded Wq,Wk,Wv,Wp

// ---------------- helpers ----------------------------------------------------
__device__ __forceinline__ uint32_t f2tf32(float f) {
    uint32_t u; asm("cvt.rna.tf32.f32 %0, %1;" : "=r"(u) : "f"(f)); return u;
}
__device__ __forceinline__ float rtf(float f) { return __uint_as_float(f2tf32(f)); }
__device__ __forceinline__ float ex2f(float x) {
    float y; asm("ex2.approx.f32 %0, %1;" : "=f"(y) : "f"(x)); return y;
}
__device__ __forceinline__ void mma8(float* d, const uint32_t* a, uint32_t b0, uint32_t b1) {
    asm volatile(
        "mma.sync.aligned.m16n8k8.row.col.f32.tf32.tf32.f32 "
        "{%0,%1,%2,%3},{%4,%5,%6,%7},{%8,%9},{%0,%1,%2,%3};"
        : "+f"(d[0]), "+f"(d[1]), "+f"(d[2]), "+f"(d[3])
        : "r"(a[0]), "r"(a[1]), "r"(a[2]), "r"(a[3]), "r"(b0), "r"(b1));
}
__device__ __forceinline__ uint32_t smem_u32(const void* p) {
    uint32_t a;
    asm("{ .reg .u64 t; cvta.to.shared.u64 t, %1; cvt.u32.u64 %0, t; }" : "=r"(a) : "l"(p));
    return a;
}
#define CP16(dst, src)  asm volatile("cp.async.cg.shared.global [%0], [%1], 16;" :: "r"(dst), "l"(src))
#define CP_COMMIT()     asm volatile("cp.async.commit_group;" ::: "memory")
#define CP_WAIT1()      asm volatile("cp.async.wait_group 1;" ::: "memory")

// ---------------------------------------------------------------------------
// Pre-rounding pass
// ---------------------------------------------------------------------------
__global__ __launch_bounds__(256) void round_inputs(
    const float* __restrict__ x,
    const float* __restrict__ Wq, const float* __restrict__ Wk,
    const float* __restrict__ Wv, const float* __restrict__ Wp)
{
    const int NX4 = (NTOT * C_) / 4;
    const int NW4 = (C_ * C_) / 4;
    for (int idx = blockIdx.x * 256 + threadIdx.x; idx < NX4 + 4 * NW4;
         idx += gridDim.x * 256) {
        float4 v; float* dst;
        if (idx < NX4) {
            v = ((const float4*)x)[idx];
            dst = g_xr + (size_t)idx * 4;
        } else {
            int w = idx - NX4, z = w / NW4, o = w - z * NW4;
            const float* src = (z == 0) ? Wq : (z == 1) ? Wk : (z == 2) ? Wv : Wp;
            v = ((const float4*)src)[o];
            dst = g_wr + (size_t)z * 65536 + (size_t)o * 4;
        }
        dst[0] = rtf(v.x); dst[1] = rtf(v.y); dst[2] = rtf(v.z); dst[3] = rtf(v.w);
    }
}

// ---------------------------------------------------------------------------
// tf32 GEMM (round-10 proven, unchanged)
// ---------------------------------------------------------------------------
#define GSM_STRIDE 40
#define GSM_BUF (128 * GSM_STRIDE)
#define GEMM_SMEM (4 * GSM_BUF * 4)     // 81920 bytes

__device__ __forceinline__ void gemm_tc_core(
    const float* __restrict__ A, const int* __restrict__ gidx,
    const float* __restrict__ W, const float* __restrict__ bias,
    float* __restrict__ outp, int m0, int n0, uint32_t* smg)
{
    const uint32_t sbase = smem_u32(smg);
    const int tid = threadIdx.x;
    const int rb = tid >> 3, kq = tid & 7;

    const float* asrc[8];
#pragma unroll
    for (int l = 0; l < 8; l++)
        asrc[l] = A + (size_t)gidx[m0 + rb + 16 * l] * 256 + kq * 4;
    const float* wbase = W + (size_t)(n0 + rb) * 256 + kq * 4;
    const uint32_t adst0 = sbase + (rb * GSM_STRIDE + kq * 4) * 4;
    const uint32_t wdst0 = adst0 + 2 * GSM_BUF * 4;

    auto stage = [&](int ch, int buf) {
        const int kof = ch * 32;
        const uint32_t bof = buf * GSM_BUF * 4;
#pragma unroll
        for (int l = 0; l < 8; l++)
            CP16(adst0 + bof + l * (16 * GSM_STRIDE * 4), asrc[l] + kof);
#pragma unroll
        for (int l = 0; l < 8; l++)
            CP16(wdst0 + bof + l * (16 * GSM_STRIDE * 4), wbase + kof + l * 4096);
    };

    const int warp = tid >> 5, lane = tid & 31;
    const int g = lane >> 2, c = lane & 3;
    const int wm = warp >> 1, wn = warp & 1;
    const int mb = wm * 64, nb = wn * 64;

    float acc[4][8][4];
#pragma unroll
    for (int mi = 0; mi < 4; mi++)
#pragma unroll
        for (int ni = 0; ni < 8; ni++)
#pragma unroll
            for (int t = 0; t < 4; t++) acc[mi][ni][t] = 0.f;

    stage(0, 0); CP_COMMIT();
    stage(1, 1); CP_COMMIT();
    CP_WAIT1(); __syncthreads();

    for (int ch = 0; ch < 8; ch++) {
        const uint32_t* Ab = smg + (ch & 1) * GSM_BUF;
        const uint32_t* Wb = smg + 2 * GSM_BUF + (ch & 1) * GSM_BUF;
#pragma unroll
        for (int kt = 0; kt < 4; kt++) {
            const int kc = kt * 8 + c * 2;
            uint32_t af[4][4];
#pragma unroll
            for (int mi = 0; mi < 4; mi++) {
                const int r = mb + mi * 16 + g;
                uint2 a0 = *(const uint2*)&Ab[r * GSM_STRIDE + kc];
                uint2 a1 = *(const uint2*)&Ab[(r + 8) * GSM_STRIDE + kc];
                af[mi][0] = a0.x; af[mi][1] = a1.x;
                af[mi][2] = a0.y; af[mi][3] = a1.y;
            }
            uint2 bf[8];
#pragma unroll
            for (int ni = 0; ni < 8; ni++)
                bf[ni] = *(const uint2*)&Wb[(nb + ni * 8 + g) * GSM_STRIDE + kc];
#pragma unroll
            for (int mi = 0; mi < 4; mi++)
#pragma unroll
                for (int ni = 0; ni < 8; ni++)
                    mma8(acc[mi][ni], af[mi], bf[ni].x, bf[ni].y);
        }
        __syncthreads();
        if (ch < 6) { stage(ch + 2, ch & 1); CP_COMMIT(); }
        if (ch < 7) { CP_WAIT1(); __syncthreads(); }
    }

    float2 bz[8];
#pragma unroll
    for (int ni = 0; ni < 8; ni++)
        bz[ni] = *(const float2*)&bias[n0 + nb + ni * 8 + 2 * c];

#pragma unroll
    for (int mi = 0; mi < 4; mi++) {
        const int mA = m0 + mb + mi * 16 + g;
        const int mB = mA + 8;
#pragma unroll
        for (int ni = 0; ni < 8; ni++) {
            const int n = n0 + nb + ni * 8 + 2 * c;
            float2 v0 = make_float2(acc[mi][ni][0] + bz[ni].x, acc[mi][ni][1] + bz[ni].y);
            float2 v1 = make_float2(acc[mi][ni][2] + bz[ni].x, acc[mi][ni][3] + bz[ni].y);
            *(float2*)&outp[(size_t)mA * 256 + n] = v0;
            *(float2*)&outp[(size_t)mB * 256 + n] = v1;
        }
    }
}

__global__ __launch_bounds__(128, 2) void gemm_qkv_tc(
    const int* __restrict__ pidx,
    const float* __restrict__ bq, const float* __restrict__ bk, const float* __restrict__ bv)
{
    extern __shared__ uint32_t smg[];
    const int z = blockIdx.z;
    const float* bi = (z == 0) ? bq : (z == 1 ? bk : bv);
    gemm_tc_core(g_xr, pidx, g_wr + (size_t)z * 65536, bi,
                 g_qkv + (size_t)z * QKV_ELEMS, blockIdx.x * 128, blockIdx.y * 128, smg);
}

__global__ __launch_bounds__(128, 2) void gemm_proj_tc(
    const int* __restrict__ pinv, const float* __restrict__ bp, float* __restrict__ out)
{
    extern __shared__ uint32_t smg[];
    gemm_tc_core(g_y, pinv, g_wr + 3 * 65536, bp, out,
                 blockIdx.x * 128, blockIdx.y * 128, smg);
}

// ---------------------------------------------------------------------------
// Attention: 256 threads, 8 warps x 64 queries, processed as 2 passes of
// TWO 16-query m-tiles -> each K/V smem fragment feeds both tiles (K+V smem
// bytes halved). Ks [512][40] k-permuted, Vs [512][36], per-warp P [32][68].
// ---------------------------------------------------------------------------
#define KS_OFF 0
#define VS_OFF (512*40)
#define PS_OFF (VS_OFF + 512*36)
#define SEG_OFF (PS_OFF + 8*(32*68))
#define ATTN_SMEM ((SEG_OFF + 512) * 4)    // 227328 bytes

__global__ __launch_bounds__(256, 1) void attn_kernel(const int* __restrict__ pbatch)
{
    extern __shared__ uint32_t sm[];
    uint32_t* Ks = sm + KS_OFF;
    uint32_t* Vs = sm + VS_OFF;
    uint32_t* Ps = sm + PS_OFF;
    int*      seg = (int*)(sm + SEG_OFF);

    const int h = blockIdx.x, b = blockIdx.y;
    const float* __restrict__ Qb = g_qkv + (size_t)(b * 512) * 256 + h * 32;
    const float* __restrict__ Kb = Qb + QKV_ELEMS;
    const float* __restrict__ Vb = Qb + 2 * (size_t)QKV_ELEMS;

    const int tid = threadIdx.x;

#pragma unroll
    for (int it = 0; it < 16; it++) {
        int idx = tid + it * 256;
        int j = idx >> 3, sub = idx & 7;
        int gq = sub >> 1, ph2 = sub & 1;
        const float* kr = Kb + (size_t)j * 256 + gq * 8 + 2 * ph2;
        float2 lo = *(const float2*)kr;
        float2 hi = *(const float2*)(kr + 4);
        uint4 v = make_uint4(f2tf32(lo.x), f2tf32(hi.x), f2tf32(lo.y), f2tf32(hi.y));
        *(uint4*)&Ks[j * 40 + gq * 8 + 4 * ph2] = v;
    }
#pragma unroll
    for (int it = 0; it < 16; it++) {
        int idx = tid + it * 256;
        int j = idx >> 3, d4 = idx & 7;
        float4 vv = *(const float4*)(Vb + (size_t)j * 256 + d4 * 4);
        uint4 v = make_uint4(f2tf32(vv.x), f2tf32(vv.y), f2tf32(vv.z), f2tf32(vv.w));
        *(uint4*)&Vs[j * 36 + d4 * 4] = v;
    }
    for (int i = tid; i < 512; i += 256) seg[i] = pbatch[b * 512 + i];
    __syncthreads();

    const int warp = tid >> 5, lane = tid & 31;
    const int g = lane >> 2, c = lane & 3;
    uint32_t* Pw = Ps + warp * (32 * 68);      // [32][68]: rows 0-15 tile0, 16-31 tile1
    const float scale = 0.17677669529663688f * 1.4426950408889634f; // 1/sqrt(32)*log2e

    for (int grp = 0; grp < 2; grp++) {
        const int q0 = warp * 64 + grp * 32;   // 32 queries: tile0 q0..q0+15, tile1 q0+16..q0+31
        int rr[2][2]; int sq[2][2];
        uint32_t aq[2][4][4];
#pragma unroll
        for (int t = 0; t < 2; t++) {
            rr[t][0] = q0 + t * 16 + g;
            rr[t][1] = rr[t][0] + 8;
            sq[t][0] = seg[rr[t][0]];
            sq[t][1] = seg[rr[t][1]];
            const float* Q0 = Qb + (size_t)rr[t][0] * 256;
            const float* Q1 = Qb + (size_t)rr[t][1] * 256;
#pragma unroll
            for (int kt = 0; kt < 4; kt++) {
                aq[t][kt][0] = f2tf32(Q0[kt*8 + c] * scale);
                aq[t][kt][1] = f2tf32(Q1[kt*8 + c] * scale);
                aq[t][kt][2] = f2tf32(Q0[kt*8 + c + 4] * scale);
                aq[t][kt][3] = f2tf32(Q1[kt*8 + c + 4] * scale);
            }
        }

        float l[2][2] = {{0.f, 0.f}, {0.f, 0.f}};
        float y[2][4][4];
#pragma unroll
        for (int t = 0; t < 2; t++)
#pragma unroll
            for (int n = 0; n < 4; n++)
#pragma unroll
                for (int r = 0; r < 4; r++) y[t][n][r] = 0.f;

        for (int ch = 0; ch < 4; ch++) {       // 128-wide j chunks
            const int j0 = ch * 128;
            float s[2][16][4];
            // ---- QK: K fragments shared by both tiles ----
#pragma unroll
            for (int nt = 0; nt < 16; nt++) {
                s[0][nt][0] = s[0][nt][1] = s[0][nt][2] = s[0][nt][3] = 0.f;
                s[1][nt][0] = s[1][nt][1] = s[1][nt][2] = s[1][nt][3] = 0.f;
                const int jb = (j0 + nt*8 + g) * 40;
#pragma unroll
                for (int kt = 0; kt < 4; kt++) {
                    uint2 kk = *(const uint2*)&Ks[jb + kt*8 + c*2];
                    mma8(s[0][nt], aq[0][kt], kk.x, kk.y);
                    mma8(s[1][nt], aq[1][kt], kk.x, kk.y);
                }
            }
            // ---- mask + exp2 ----
#pragma unroll
            for (int nt = 0; nt < 16; nt++) {
                int2 sp = *(const int2*)&seg[j0 + nt*8 + 2*c];
#pragma unroll
                for (int t = 0; t < 2; t++) {
                    float p0 = ex2f((sp.x == sq[t][0]) ? -72.f : s[t][nt][0]);
                    float p1 = ex2f((sp.y == sq[t][0]) ? -72.f : s[t][nt][1]);
                    float p2 = ex2f((sp.x == sq[t][1]) ? -72.f : s[t][nt][2]);
                    float p3 = ex2f((sp.y == sq[t][1]) ? -72.f : s[t][nt][3]);
                    s[t][nt][0] = p0; s[t][nt][1] = p1;
                    s[t][nt][2] = p2; s[t][nt][3] = p3;
                    l[t][0] += p0 + p1; l[t][1] += p2 + p3;
                }
            }

            // ---- PV: V fragments shared by both tiles ----
#pragma unroll
            for (int hf = 0; hf < 2; hf++) {
                __syncwarp();
#pragma unroll
                for (int nt2 = 0; nt2 < 8; nt2++) {
                    const int nt = hf * 8 + nt2;
#pragma unroll
                    for (int t = 0; t < 2; t++) {
                        Pw[(t*16 + g)*68     + nt2*8 + 2*c    ] = f2tf32(s[t][nt][0]);
                        Pw[(t*16 + g)*68     + nt2*8 + 2*c + 1] = f2tf32(s[t][nt][1]);
                        Pw[(t*16 + g + 8)*68 + nt2*8 + 2*c    ] = f2tf32(s[t][nt][2]);
                        Pw[(t*16 + g + 8)*68 + nt2*8 + 2*c + 1] = f2tf32(s[t][nt][3]);
                    }
                }
                __syncwarp();
                const int jh = j0 + hf * 64;
#pragma unroll
                for (int kt2 = 0; kt2 < 8; kt2++) {
                    uint32_t ap0[4], ap1[4];
                    ap0[0] = Pw[g*68        + kt2*8 + c];
                    ap0[1] = Pw[(g+8)*68    + kt2*8 + c];
                    ap0[2] = Pw[g*68        + kt2*8 + c + 4];
                    ap0[3] = Pw[(g+8)*68    + kt2*8 + c + 4];
                    ap1[0] = Pw[(16+g)*68   + kt2*8 + c];
                    ap1[1] = Pw[(24+g)*68   + kt2*8 + c];
                    ap1[2] = Pw[(16+g)*68   + kt2*8 + c + 4];
                    ap1[3] = Pw[(24+g)*68   + kt2*8 + c + 4];
                    const int vb0 = (jh + kt2*8 + c) * 36 + g;
                    const int vb1 = (jh + kt2*8 + c + 4) * 36 + g;
#pragma unroll
                    for (int nt2 = 0; nt2 < 4; nt2++) {
                        uint32_t v0 = Vs[vb0 + nt2*8], v1 = Vs[vb1 + nt2*8];
                        mma8(y[0][nt2], ap0, v0, v1);
                        mma8(y[1][nt2], ap1, v0, v1);
                    }
                }
            }
        }

#pragma unroll
        for (int t = 0; t < 2; t++) {
            float l0 = l[t][0], l1 = l[t][1];
            l0 += __shfl_xor_sync(0xffffffffu, l0, 1);
            l0 += __shfl_xor_sync(0xffffffffu, l0, 2);
            l1 += __shfl_xor_sync(0xffffffffu, l1, 1);
            l1 += __shfl_xor_sync(0xffffffffu, l1, 2);
            const float inv0 = 1.0f / l0, inv1 = 1.0f / l1;

            float* O0 = g_y + (size_t)(b * 512 + rr[t][0]) * 256 + h * 32;
            float* O1 = g_y + (size_t)(b * 512 + rr[t][1]) * 256 + h * 32;
#pragma unroll
            for (int nt2 = 0; nt2 < 4; nt2++) {
                float2 v0 = make_float2(rtf(y[t][nt2][0] * inv0), rtf(y[t][nt2][1] * inv0));
                float2 v1 = make_float2(rtf(y[t][nt2][2] * inv1), rtf(y[t][nt2][3] * inv1));
                *(float2*)&O0[nt2*8 + 2*c] = v0;
                *(float2*)&O1[nt2*8 + 2*c] = v1;
            }
        }
    }
}

// ---------------------------------------------------------------------------

extern "C" void kernel_launch(void* const* d_in, const int* in_sizes, int n_in,
                              void* d_out, int out_size)
{
    const float* x    = (const float*)d_in[0];
    const float* Wq   = (const float*)d_in[1];
    const float* bq   = (const float*)d_in[2];
    const float* Wk   = (const float*)d_in[3];
    const float* bk   = (const float*)d_in[4];
    const float* Wv   = (const float*)d_in[5];
    const float* bv   = (const float*)d_in[6];
    const float* Wp   = (const float*)d_in[7];
    const float* bp   = (const float*)d_in[8];
    const int* pidx   = (const int*)d_in[9];
    const int* pbatch = (const int*)d_in[10];
    const int* pinv   = (const int*)d_in[11];
    float* out = (float*)d_out;

    cudaFuncSetAttribute(gemm_qkv_tc,  cudaFuncAttributeMaxDynamicSharedMemorySize, GEMM_SMEM);
    cudaFuncSetAttribute(gemm_proj_tc, cudaFuncAttributeMaxDynamicSharedMemorySize, GEMM_SMEM);
    cudaFuncSetAttribute(attn_kernel,  cudaFuncAttributeMaxDynamicSharedMemorySize, ATTN_SMEM);

    round_inputs<<<1024, 256>>>(x, Wq, Wk, Wv, Wp);
    gemm_qkv_tc<<<dim3(M_ / 128, 2, 3), 128, GEMM_SMEM>>>(pidx, bq, bk, bv);
    attn_kernel<<<dim3(H_, B_), 256, ATTN_SMEM>>>(pbatch);
    gemm_proj_tc<<<dim3(NTOT / 128, 2), 128, GEMM_SMEM>>>(pinv, bp, out);
}

// round 13
// speedup vs baseline: 1.5030x; 1.0641x over previous
#include <cuda_runtime.h>
#include <cstdint>

#define B_    64
#define T_    512
#define H_    8
#define D_    32
#define C_    256
#define M_    (B_*T_)
#define NTOT  24576
#define QKV_ELEMS (NTOT*C_)

__device__ float g_qkv[3 * QKV_ELEMS];   // q,k,v each [token][256] (per DISTINCT token)
__device__ float g_y[M_ * C_];           // attention out per packed slot (tf32-rounded)
__device__ float g_xr[NTOT * C_];        // tf32-rounded x
__device__ float g_wr[4 * C_ * C_];      // tf32-rounded Wq,Wk,Wv,Wp

// ---------------- helpers ----------------------------------------------------
__device__ __forceinline__ uint32_t f2tf32(float f) {
    uint32_t u; asm("cvt.rna.tf32.f32 %0, %1;" : "=r"(u) : "f"(f)); return u;
}
__device__ __forceinline__ float rtf(float f) { return __uint_as_float(f2tf32(f)); }
__device__ __forceinline__ float ex2f(float x) {
    float y; asm("ex2.approx.f32 %0, %1;" : "=f"(y) : "f"(x)); return y;
}
__device__ __forceinline__ void mma8(float* d, const uint32_t* a, uint32_t b0, uint32_t b1) {
    asm volatile(
        "mma.sync.aligned.m16n8k8.row.col.f32.tf32.tf32.f32 "
        "{%0,%1,%2,%3},{%4,%5,%6,%7},{%8,%9},{%0,%1,%2,%3};"
        : "+f"(d[0]), "+f"(d[1]), "+f"(d[2]), "+f"(d[3])
        : "r"(a[0]), "r"(a[1]), "r"(a[2]), "r"(a[3]), "r"(b0), "r"(b1));
}
__device__ __forceinline__ uint32_t smem_u32(const void* p) {
    uint32_t a;
    asm("{ .reg .u64 t; cvta.to.shared.u64 t, %1; cvt.u32.u64 %0, t; }" : "=r"(a) : "l"(p));
    return a;
}
#define CP16(dst, src)  asm volatile("cp.async.cg.shared.global [%0], [%1], 16;" :: "r"(dst), "l"(src))
#define CP_COMMIT()     asm volatile("cp.async.commit_group;" ::: "memory")
#define CP_WAIT1()      asm volatile("cp.async.wait_group 1;" ::: "memory")

// ---------------------------------------------------------------------------
// Pre-rounding pass
// ---------------------------------------------------------------------------
__global__ __launch_bounds__(256) void round_inputs(
    const float* __restrict__ x,
    const float* __restrict__ Wq, const float* __restrict__ Wk,
    const float* __restrict__ Wv, const float* __restrict__ Wp)
{
    const int NX4 = (NTOT * C_) / 4;
    const int NW4 = (C_ * C_) / 4;
    for (int idx = blockIdx.x * 256 + threadIdx.x; idx < NX4 + 4 * NW4;
         idx += gridDim.x * 256) {
        float4 v; float* dst;
        if (idx < NX4) {
            v = ((const float4*)x)[idx];
            dst = g_xr + (size_t)idx * 4;
        } else {
            int w = idx - NX4, z = w / NW4, o = w - z * NW4;
            const float* src = (z == 0) ? Wq : (z == 1) ? Wk : (z == 2) ? Wv : Wp;
            v = ((const float4*)src)[o];
            dst = g_wr + (size_t)z * 65536 + (size_t)o * 4;
        }
        dst[0] = rtf(v.x); dst[1] = rtf(v.y); dst[2] = rtf(v.z); dst[3] = rtf(v.w);
    }
}

// ---------------------------------------------------------------------------
// tf32 GEMM (round-10 proven); gidx==nullptr -> sequential A rows
// ---------------------------------------------------------------------------
#define GSM_STRIDE 40
#define GSM_BUF (128 * GSM_STRIDE)
#define GEMM_SMEM (4 * GSM_BUF * 4)     // 81920 bytes

__device__ __forceinline__ void gemm_tc_core(
    const float* __restrict__ A, const int* __restrict__ gidx,
    const float* __restrict__ W, const float* __restrict__ bias,
    float* __restrict__ outp, int m0, int n0, uint32_t* smg)
{
    const uint32_t sbase = smem_u32(smg);
    const int tid = threadIdx.x;
    const int rb = tid >> 3, kq = tid & 7;

    const float* asrc[8];
#pragma unroll
    for (int l = 0; l < 8; l++) {
        int row = m0 + rb + 16 * l;
        if (gidx) row = gidx[row];
        asrc[l] = A + (size_t)row * 256 + kq * 4;
    }
    const float* wbase = W + (size_t)(n0 + rb) * 256 + kq * 4;
    const uint32_t adst0 = sbase + (rb * GSM_STRIDE + kq * 4) * 4;
    const uint32_t wdst0 = adst0 + 2 * GSM_BUF * 4;

    auto stage = [&](int ch, int buf) {
        const int kof = ch * 32;
        const uint32_t bof = buf * GSM_BUF * 4;
#pragma unroll
        for (int l = 0; l < 8; l++)
            CP16(adst0 + bof + l * (16 * GSM_STRIDE * 4), asrc[l] + kof);
#pragma unroll
        for (int l = 0; l < 8; l++)
            CP16(wdst0 + bof + l * (16 * GSM_STRIDE * 4), wbase + kof + l * 4096);
    };

    const int warp = tid >> 5, lane = tid & 31;
    const int g = lane >> 2, c = lane & 3;
    const int wm = warp >> 1, wn = warp & 1;
    const int mb = wm * 64, nb = wn * 64;

    float acc[4][8][4];
#pragma unroll
    for (int mi = 0; mi < 4; mi++)
#pragma unroll
        for (int ni = 0; ni < 8; ni++)
#pragma unroll
            for (int t = 0; t < 4; t++) acc[mi][ni][t] = 0.f;

    stage(0, 0); CP_COMMIT();
    stage(1, 1); CP_COMMIT();
    CP_WAIT1(); __syncthreads();

    for (int ch = 0; ch < 8; ch++) {
        const uint32_t* Ab = smg + (ch & 1) * GSM_BUF;
        const uint32_t* Wb = smg + 2 * GSM_BUF + (ch & 1) * GSM_BUF;
#pragma unroll
        for (int kt = 0; kt < 4; kt++) {
            const int kc = kt * 8 + c * 2;
            uint32_t af[4][4];
#pragma unroll
            for (int mi = 0; mi < 4; mi++) {
                const int r = mb + mi * 16 + g;
                uint2 a0 = *(const uint2*)&Ab[r * GSM_STRIDE + kc];
                uint2 a1 = *(const uint2*)&Ab[(r + 8) * GSM_STRIDE + kc];
                af[mi][0] = a0.x; af[mi][1] = a1.x;
                af[mi][2] = a0.y; af[mi][3] = a1.y;
            }
            uint2 bf[8];
#pragma unroll
            for (int ni = 0; ni < 8; ni++)
                bf[ni] = *(const uint2*)&Wb[(nb + ni * 8 + g) * GSM_STRIDE + kc];
#pragma unroll
            for (int mi = 0; mi < 4; mi++)
#pragma unroll
                for (int ni = 0; ni < 8; ni++)
                    mma8(acc[mi][ni], af[mi], bf[ni].x, bf[ni].y);
        }
        __syncthreads();
        if (ch < 6) { stage(ch + 2, ch & 1); CP_COMMIT(); }
        if (ch < 7) { CP_WAIT1(); __syncthreads(); }
    }

    float2 bz[8];
#pragma unroll
    for (int ni = 0; ni < 8; ni++)
        bz[ni] = *(const float2*)&bias[n0 + nb + ni * 8 + 2 * c];

#pragma unroll
    for (int mi = 0; mi < 4; mi++) {
        const int mA = m0 + mb + mi * 16 + g;
        const int mB = mA + 8;
#pragma unroll
        for (int ni = 0; ni < 8; ni++) {
            const int n = n0 + nb + ni * 8 + 2 * c;
            float2 v0 = make_float2(acc[mi][ni][0] + bz[ni].x, acc[mi][ni][1] + bz[ni].y);
            float2 v1 = make_float2(acc[mi][ni][2] + bz[ni].x, acc[mi][ni][3] + bz[ni].y);
            *(float2*)&outp[(size_t)mA * 256 + n] = v0;
            *(float2*)&outp[(size_t)mB * 256 + n] = v1;
        }
    }
}

__global__ __launch_bounds__(128, 2) void gemm_qkv_tc(
    const float* __restrict__ bq, const float* __restrict__ bk, const float* __restrict__ bv)
{
    extern __shared__ uint32_t smg[];
    const int z = blockIdx.z;
    const float* bi = (z == 0) ? bq : (z == 1 ? bk : bv);
    gemm_tc_core(g_xr, nullptr, g_wr + (size_t)z * 65536, bi,
                 g_qkv + (size_t)z * QKV_ELEMS, blockIdx.x * 128, blockIdx.y * 128, smg);
}

__global__ __launch_bounds__(128, 2) void gemm_proj_tc(
    const int* __restrict__ pinv, const float* __restrict__ bp, float* __restrict__ out)
{
    extern __shared__ uint32_t smg[];
    gemm_tc_core(g_y, pinv, g_wr + 3 * 65536, bp, out,
                 blockIdx.x * 128, blockIdx.y * 128, smg);
}

// ---------------------------------------------------------------------------
// Attention (round-12 proven structure); K/V/Q rows now gathered via pidx
// (qkv computed per distinct token). Ks [512][40] permuted, Vs [512][36],
// per-warp P [32][68], two 16-q m-tiles per pass.
// ---------------------------------------------------------------------------
#define KS_OFF 0
#define VS_OFF (512*40)
#define PS_OFF (VS_OFF + 512*36)
#define SEG_OFF (PS_OFF + 8*(32*68))
#define ATTN_SMEM ((SEG_OFF + 512) * 4)    // 227328 bytes

__global__ __launch_bounds__(256, 1) void attn_kernel(
    const int* __restrict__ pbatch, const int* __restrict__ pidx)
{
    extern __shared__ uint32_t sm[];
    uint32_t* Ks = sm + KS_OFF;
    uint32_t* Vs = sm + VS_OFF;
    uint32_t* Ps = sm + PS_OFF;
    int*      seg = (int*)(sm + SEG_OFF);

    const int h = blockIdx.x, b = blockIdx.y;
    const int tid = threadIdx.x;

    // K (permuted) + V (identity) staging, rows gathered via pidx
#pragma unroll
    for (int it = 0; it < 16; it++) {
        int idx = tid + it * 256;            // 0..4095
        int j = idx >> 3, sub = idx & 7;
        int tok = pidx[(b << 9) + j];
        const float* base = g_qkv + (size_t)tok * 256 + h * 32;
        int gq = sub >> 1, ph2 = sub & 1;
        const float* kr = base + QKV_ELEMS + gq * 8 + 2 * ph2;
        float2 lo = *(const float2*)kr;
        float2 hi = *(const float2*)(kr + 4);
        uint4 kv = make_uint4(f2tf32(lo.x), f2tf32(hi.x), f2tf32(lo.y), f2tf32(hi.y));
        *(uint4*)&Ks[j * 40 + gq * 8 + 4 * ph2] = kv;
        float4 vv = *(const float4*)(base + 2 * (size_t)QKV_ELEMS + sub * 4);
        uint4 v = make_uint4(f2tf32(vv.x), f2tf32(vv.y), f2tf32(vv.z), f2tf32(vv.w));
        *(uint4*)&Vs[j * 36 + sub * 4] = v;
    }
    for (int i = tid; i < 512; i += 256) seg[i] = pbatch[b * 512 + i];
    __syncthreads();

    const int warp = tid >> 5, lane = tid & 31;
    const int g = lane >> 2, c = lane & 3;
    uint32_t* Pw = Ps + warp * (32 * 68);
    const float scale = 0.17677669529663688f * 1.4426950408889634f;

    for (int grp = 0; grp < 2; grp++) {
        const int q0 = warp * 64 + grp * 32;
        int rr[2][2]; int sq[2][2];
        uint32_t aq[2][4][4];
#pragma unroll
        for (int t = 0; t < 2; t++) {
            rr[t][0] = q0 + t * 16 + g;
            rr[t][1] = rr[t][0] + 8;
            sq[t][0] = seg[rr[t][0]];
            sq[t][1] = seg[rr[t][1]];
            const float* Q0 = g_qkv + (size_t)pidx[(b << 9) + rr[t][0]] * 256 + h * 32;
            const float* Q1 = g_qkv + (size_t)pidx[(b << 9) + rr[t][1]] * 256 + h * 32;
#pragma unroll
            for (int kt = 0; kt < 4; kt++) {
                aq[t][kt][0] = f2tf32(Q0[kt*8 + c] * scale);
                aq[t][kt][1] = f2tf32(Q1[kt*8 + c] * scale);
                aq[t][kt][2] = f2tf32(Q0[kt*8 + c + 4] * scale);
                aq[t][kt][3] = f2tf32(Q1[kt*8 + c + 4] * scale);
            }
        }

        float l[2][2] = {{0.f, 0.f}, {0.f, 0.f}};
        float y[2][4][4];
#pragma unroll
        for (int t = 0; t < 2; t++)
#pragma unroll
            for (int n = 0; n < 4; n++)
#pragma unroll
                for (int r = 0; r < 4; r++) y[t][n][r] = 0.f;

        for (int ch = 0; ch < 4; ch++) {
            const int j0 = ch * 128;
            float s[2][16][4];
#pragma unroll
            for (int nt = 0; nt < 16; nt++) {
                s[0][nt][0] = s[0][nt][1] = s[0][nt][2] = s[0][nt][3] = 0.f;
                s[1][nt][0] = s[1][nt][1] = s[1][nt][2] = s[1][nt][3] = 0.f;
                const int jb = (j0 + nt*8 + g) * 40;
#pragma unroll
                for (int kt = 0; kt < 4; kt++) {
                    uint2 kk = *(const uint2*)&Ks[jb + kt*8 + c*2];
                    mma8(s[0][nt], aq[0][kt], kk.x, kk.y);
                    mma8(s[1][nt], aq[1][kt], kk.x, kk.y);
                }
            }
#pragma unroll
            for (int nt = 0; nt < 16; nt++) {
                int2 sp = *(const int2*)&seg[j0 + nt*8 + 2*c];
#pragma unroll
                for (int t = 0; t < 2; t++) {
                    float p0 = ex2f((sp.x == sq[t][0]) ? -72.f : s[t][nt][0]);
                    float p1 = ex2f((sp.y == sq[t][0]) ? -72.f : s[t][nt][1]);
                    float p2 = ex2f((sp.x == sq[t][1]) ? -72.f : s[t][nt][2]);
                    float p3 = ex2f((sp.y == sq[t][1]) ? -72.f : s[t][nt][3]);
                    s[t][nt][0] = p0; s[t][nt][1] = p1;
                    s[t][nt][2] = p2; s[t][nt][3] = p3;
                    l[t][0] += p0 + p1; l[t][1] += p2 + p3;
                }
            }

#pragma unroll
            for (int hf = 0; hf < 2; hf++) {
                __syncwarp();
#pragma unroll
                for (int nt2 = 0; nt2 < 8; nt2++) {
                    const int nt = hf * 8 + nt2;
#pragma unroll
                    for (int t = 0; t < 2; t++) {
                        Pw[(t*16 + g)*68     + nt2*8 + 2*c    ] = f2tf32(s[t][nt][0]);
                        Pw[(t*16 + g)*68     + nt2*8 + 2*c + 1] = f2tf32(s[t][nt][1]);
                        Pw[(t*16 + g + 8)*68 + nt2*8 + 2*c    ] = f2tf32(s[t][nt][2]);
                        Pw[(t*16 + g + 8)*68 + nt2*8 + 2*c + 1] = f2tf32(s[t][nt][3]);
                    }
                }
                __syncwarp();
                const int jh = j0 + hf * 64;
#pragma unroll
                for (int kt2 = 0; kt2 < 8; kt2++) {
                    uint32_t ap0[4], ap1[4];
                    ap0[0] = Pw[g*68        + kt2*8 + c];
                    ap0[1] = Pw[(g+8)*68    + kt2*8 + c];
                    ap0[2] = Pw[g*68        + kt2*8 + c + 4];
                    ap0[3] = Pw[(g+8)*68    + kt2*8 + c + 4];
                    ap1[0] = Pw[(16+g)*68   + kt2*8 + c];
                    ap1[1] = Pw[(24+g)*68   + kt2*8 + c];
                    ap1[2] = Pw[(16+g)*68   + kt2*8 + c + 4];
                    ap1[3] = Pw[(24+g)*68   + kt2*8 + c + 4];
                    const int vb0 = (jh + kt2*8 + c) * 36 + g;
                    const int vb1 = (jh + kt2*8 + c + 4) * 36 + g;
#pragma unroll
                    for (int nt2 = 0; nt2 < 4; nt2++) {
                        uint32_t v0 = Vs[vb0 + nt2*8], v1 = Vs[vb1 + nt2*8];
                        mma8(y[0][nt2], ap0, v0, v1);
                        mma8(y[1][nt2], ap1, v0, v1);
                    }
                }
            }
        }

#pragma unroll
        for (int t = 0; t < 2; t++) {
            float l0 = l[t][0], l1 = l[t][1];
            l0 += __shfl_xor_sync(0xffffffffu, l0, 1);
            l0 += __shfl_xor_sync(0xffffffffu, l0, 2);
            l1 += __shfl_xor_sync(0xffffffffu, l1, 1);
            l1 += __shfl_xor_sync(0xffffffffu, l1, 2);
            const float inv0 = 1.0f / l0, inv1 = 1.0f / l1;

            float* O0 = g_y + (size_t)(b * 512 + rr[t][0]) * 256 + h * 32;
            float* O1 = g_y + (size_t)(b * 512 + rr[t][1]) * 256 + h * 32;
#pragma unroll
            for (int nt2 = 0; nt2 < 4; nt2++) {
                float2 v0 = make_float2(rtf(y[t][nt2][0] * inv0), rtf(y[t][nt2][1] * inv0));
                float2 v1 = make_float2(rtf(y[t][nt2][2] * inv1), rtf(y[t][nt2][3] * inv1));
                *(float2*)&O0[nt2*8 + 2*c] = v0;
                *(float2*)&O1[nt2*8 + 2*c] = v1;
            }
        }
    }
}

// ---------------------------------------------------------------------------

extern "C" void kernel_launch(void* const* d_in, const int* in_sizes, int n_in,
                              void* d_out, int out_size)
{
    const float* x    = (const float*)d_in[0];
    const float* Wq   = (const float*)d_in[1];
    const float* bq   = (const float*)d_in[2];
    const float* Wk   = (const float*)d_in[3];
    const float* bk   = (const float*)d_in[4];
    const float* Wv   = (const float*)d_in[5];
    const float* bv   = (const float*)d_in[6];
    const float* Wp   = (const float*)d_in[7];
    const float* bp   = (const float*)d_in[8];
    const int* pidx   = (const int*)d_in[9];
    const int* pbatch = (const int*)d_in[10];
    const int* pinv   = (const int*)d_in[11];
    float* out = (float*)d_out;

    cudaFuncSetAttribute(gemm_qkv_tc,  cudaFuncAttributeMaxDynamicSharedMemorySize, GEMM_SMEM);
    cudaFuncSetAttribute(gemm_proj_tc, cudaFuncAttributeMaxDynamicSharedMemorySize, GEMM_SMEM);
    cudaFuncSetAttribute(attn_kernel,  cudaFuncAttributeMaxDynamicSharedMemorySize, ATTN_SMEM);

    round_inputs<<<1024, 256>>>(x, Wq, Wk, Wv, Wp);
    gemm_qkv_tc<<<dim3(NTOT / 128, 2, 3), 128, GEMM_SMEM>>>(bq, bk, bv);
    attn_kernel<<<dim3(H_, B_), 256, ATTN_SMEM>>>(pbatch, pidx);
    gemm_proj_tc<<<dim3(NTOT / 128, 2), 128, GEMM_SMEM>>>(pinv, bp, out);
}